// round 14
// baseline (speedup 1.0000x reference)
#include <cuda_runtime.h>
#include <cuda_bf16.h>
#include <math.h>
#include <stdint.h>

typedef unsigned long long ull;

#define BT    65536
#define T_LEN 16384
#define RCH   128
#define TM    64
#define NT    128

// ---------------- scratch ---------------------------------------------------
__device__ float g_resA[BT * RCH];
__device__ float g_resB[BT * RCH];
__device__ float g_outacc[BT * RCH];
// prepped weights: bf16 hi/lo K-major tiles [128 n x 64 k] (8192 elems each)
// fg per layer: tile idx = gate*8 + part*4 + chunk(4)
// sr per layer: tile idx = mat*4 + part*2 + chunk(2)
__device__ __nv_bfloat16 g_wfg[20 * 16 * 8192];
__device__ __nv_bfloat16 g_wsr[20 * 8 * 8192];

// ---------------- packed f32x2 helpers (SIMT kernels) -----------------------
__device__ __forceinline__ ull pk2(float lo, float hi) {
    ull r; asm("mov.b64 %0, {%1, %2};" : "=l"(r) : "f"(lo), "f"(hi)); return r;
}
__device__ __forceinline__ void upk2(ull v, float& lo, float& hi) {
    asm("mov.b64 {%0, %1}, %2;" : "=f"(lo), "=f"(hi) : "l"(v));
}
__device__ __forceinline__ void fma2(ull& d, ull a, ull b) {
    asm("fma.rn.f32x2 %0, %1, %2, %0;" : "+l"(d) : "l"(a), "l"(b));
}
__device__ __forceinline__ ull add2(ull a, ull b) {
    ull r; asm("add.rn.f32x2 %0, %1, %2;" : "=l"(r) : "l"(a), "l"(b)); return r;
}

// ---------------- warp-mma helpers ------------------------------------------
__device__ __forceinline__ uint32_t s2u(const void* p) {
    uint32_t a;
    asm("{ .reg .u64 t; cvta.to.shared.u64 t, %1; cvt.u32.u64 %0, t; }" : "=r"(a) : "l"(p));
    return a;
}
__device__ __forceinline__ void ldm4(uint32_t* r, uint32_t addr) {
    asm volatile("ldmatrix.sync.aligned.m8n8.x4.shared.b16 {%0,%1,%2,%3}, [%4];"
                 : "=r"(r[0]), "=r"(r[1]), "=r"(r[2]), "=r"(r[3]) : "r"(addr));
}
__device__ __forceinline__ void mma16816(float* d, const uint32_t* a, uint32_t b0, uint32_t b1) {
    asm volatile("mma.sync.aligned.m16n8k16.row.col.f32.bf16.bf16.f32 "
                 "{%0,%1,%2,%3}, {%4,%5,%6,%7}, {%8,%9}, {%0,%1,%2,%3};"
                 : "+f"(d[0]), "+f"(d[1]), "+f"(d[2]), "+f"(d[3])
                 : "r"(a[0]), "r"(a[1]), "r"(a[2]), "r"(a[3]), "r"(b0), "r"(b1));
}
#define STS128(a, v) \
    asm volatile("st.shared.v4.b32 [%0], {%1,%2,%3,%4};" :: "r"(a), "r"((v).x), "r"((v).y), "r"((v).z), "r"((v).w))
#define STS32(a, v) asm volatile("st.shared.b32 [%0], %1;" :: "r"(a), "r"(v))
#define CP_ASYNC16(d, s) asm volatile("cp.async.cg.shared.global [%0], [%1], 16;" :: "r"(d), "l"(s))
#define CP_COMMIT()      asm volatile("cp.async.commit_group;" ::: "memory")
#define CP_WAIT_1()      asm volatile("cp.async.wait_group 1;" ::: "memory")
#define CP_WAIT_0()      asm volatile("cp.async.wait_group 0;" ::: "memory")

// smem layout (bytes): bias[512 f32] | A hi [64x264 bf16] | A lo | W: 2 single-tile buffers
#define SA_STRIDE 528
#define ALO_OFF   33792
#define W_STRIDE  144
#define W_TILE    18432
#define OFF_A     2048
#define OFF_W     (OFF_A + 2 * 33792)     // 69632
#define LSMEM     (OFF_W + 2 * W_TILE)    // 106496  -> 2 CTAs/SM

// ---------------------------------------------------------------------------
// Weight prep: split fp32 weights to bf16 hi/lo, transpose to [n][k] tiles.
__global__ void prep_kernel(const float* __restrict__ fw, const float* __restrict__ gw,
                            const float* __restrict__ sw, const float* __restrict__ rw)
{
    const int total_fg = 20 * 2 * 4 * 128 * 64;
    const int total_sr = 20 * 2 * 2 * 128 * 64;
    for (int idx = blockIdx.x * blockDim.x + threadIdx.x; idx < total_fg + total_sr;
         idx += gridDim.x * blockDim.x) {
        if (idx < total_fg) {
            int k = idx & 63, n = (idx >> 6) & 127, c = (idx >> 13) & 3;
            int gate = (idx >> 15) & 1, layer = idx >> 16;
            int kk = c * 64 + k, tap = kk >> 7, kc = kk & 127;
            const float* src = gate ? gw : fw;
            float w = src[(((size_t)layer * 2 + tap) * 128 + kc) * 128 + n];
            __nv_bfloat16 hi = __float2bfloat16(w);
            __nv_bfloat16 lo = __float2bfloat16(w - __bfloat162float(hi));
            size_t tbase = ((size_t)layer * 16 + gate * 8) * 8192 + (size_t)n * 64 + k;
            g_wfg[tbase + (size_t)(0 * 4 + c) * 8192] = hi;
            g_wfg[tbase + (size_t)(1 * 4 + c) * 8192] = lo;
        } else {
            int j = idx - total_fg;
            int k = j & 63, n = (j >> 6) & 127, c = (j >> 13) & 1;
            int mat = (j >> 14) & 1, layer = j >> 15;
            int kc = c * 64 + k;
            const float* src = mat ? rw : sw;
            float w = src[((size_t)layer * 128 + kc) * 128 + n];
            __nv_bfloat16 hi = __float2bfloat16(w);
            __nv_bfloat16 lo = __float2bfloat16(w - __bfloat162float(hi));
            size_t tbase = ((size_t)layer * 8 + mat * 4) * 8192 + (size_t)n * 64 + k;
            g_wsr[tbase + (size_t)(0 * 2 + c) * 8192] = hi;
            g_wsr[tbase + (size_t)(1 * 2 + c) * 8192] = lo;
        }
    }
}

// stage ONE weight tile (16 KB) into a W slot via cp.async
__device__ __forceinline__ void stage1(uint32_t dst, const __nv_bfloat16* __restrict__ src, int tid)
{
    #pragma unroll
    for (int r = 0; r < 4; r++) {
        int i = r * 256 + tid;
        int n = i >> 3, ku = i & 7;
        CP_ASYNC16(dst + n * W_STRIDE + ku * 16, src + (size_t)n * 64 + ku * 8);
    }
}

// hi-tile phase: ACC += (A_hi + A_lo) x W_hi  over k-chunk cc, W slot offset wb
#define COMPUTE_HI(ACC, cc, wb) do {                                           \
    _Pragma("unroll")                                                          \
    for (int ks = 0; ks < 4; ks++) {                                           \
        const int kA2 = ((cc) * 64 + ks * 16) * 2, kW2 = ks * 32;              \
        uint32_t ah[2][4], al[2][4], b0[4], b1[4];                             \
        ldm4(ah[0], aBase + kA2);                                              \
        ldm4(ah[1], aBase + 16 * SA_STRIDE + kA2);                             \
        ldm4(al[0], aBase + ALO_OFF + kA2);                                    \
        ldm4(al[1], aBase + ALO_OFF + 16 * SA_STRIDE + kA2);                   \
        ldm4(b0, bB + (wb) + kW2);                                             \
        ldm4(b1, bB + (wb) + 16 * W_STRIDE + kW2);                             \
        _Pragma("unroll")                                                      \
        for (int mt = 0; mt < 2; mt++)                                         \
            _Pragma("unroll")                                                  \
            for (int nq = 0; nq < 4; nq++) {                                   \
                const uint32_t* bp = (nq >> 1) ? b1 : b0;                      \
                int pr = (nq & 1) * 2;                                         \
                mma16816(ACC[mt][nq], ah[mt], bp[pr], bp[pr + 1]);             \
                mma16816(ACC[mt][nq], al[mt], bp[pr], bp[pr + 1]);             \
            }                                                                  \
    }                                                                          \
} while (0)

// lo-tile phase: ACC += A_hi x W_lo
#define COMPUTE_LO(ACC, cc, wb) do {                                           \
    _Pragma("unroll")                                                          \
    for (int ks = 0; ks < 4; ks++) {                                           \
        const int kA2 = ((cc) * 64 + ks * 16) * 2, kW2 = ks * 32;              \
        uint32_t ah[2][4], b0[4], b1[4];                                       \
        ldm4(ah[0], aBase + kA2);                                              \
        ldm4(ah[1], aBase + 16 * SA_STRIDE + kA2);                             \
        ldm4(b0, bB + (wb) + kW2);                                             \
        ldm4(b1, bB + (wb) + 16 * W_STRIDE + kW2);                             \
        _Pragma("unroll")                                                      \
        for (int mt = 0; mt < 2; mt++)                                         \
            _Pragma("unroll")                                                  \
            for (int nq = 0; nq < 4; nq++) {                                   \
                const uint32_t* bp = (nq >> 1) ? b1 : b0;                      \
                int pr = (nq & 1) * 2;                                         \
                mma16816(ACC[mt][nq], ah[mt], bp[pr], bp[pr + 1]);             \
            }                                                                  \
    }                                                                          \
} while (0)

// ---------------------------------------------------------------------------
// Tensor-core WaveNet layer. 2 CTAs/SM; tile-granular cp.async double buffer.
__global__ void __launch_bounds__(256, 2) tlayer_kernel(
    const float* __restrict__ res_in, float* __restrict__ res_out,
    float* __restrict__ out_acc,
    const __nv_bfloat16* __restrict__ wfg, const __nv_bfloat16* __restrict__ wsr,
    const float* __restrict__ fb, const float* __restrict__ gb,
    const float* __restrict__ sb, const float* __restrict__ rb,
    int d, int first)
{
    extern __shared__ char smem[];
    float* sbias = (float*)smem;
    const uint32_t sbase = s2u(smem);
    const uint32_t sA = sbase + OFF_A;
    const uint32_t sW = sbase + OFF_W;

    const int tid = threadIdx.x, wid = tid >> 5, lane = tid & 31;
    const int row0 = blockIdx.x * TM;
    const int batchStart = (row0 / T_LEN) * T_LEN;

    // fg tile t (0..15): gate=(t>>1)&1, hilo=t&1, chunk=t>>2
    // sr tile u (0..7):  mat=(u>>1)&1, hilo=u&1, chunk=u>>2
    #define FG_TILE(t) (wfg + (size_t)(((((t) >> 1) & 1) * 8) + (((t) & 1) * 4) + ((t) >> 2)) * 8192)
    #define SR_TILE(u) (wsr + (size_t)(((((u) >> 1) & 1) * 4) + (((u) & 1) * 2) + ((u) >> 2)) * 8192)

    // prefetch tile 0 while we stage A
    stage1(sW, FG_TILE(0), tid);
    CP_COMMIT();

    for (int i = tid; i < 512; i += 256) {
        int grp = i >> 7, n = i & 127;
        const float* p = grp == 0 ? fb : grp == 1 ? gb : grp == 2 ? sb : rb;
        sbias[i] = p[n];
    }

    // ---- stage A = [prev(128) | cur(128)] as bf16 hi/lo, row-major [64][264]
    for (int idx = tid; idx < 2048; idx += 256) {
        int row = idx >> 5, ch = (idx & 31) * 8;
        int srow, c2;
        if (ch < 128) { srow = row0 + row - d; c2 = ch; }
        else          { srow = row0 + row;     c2 = ch - 128; }
        float v[8];
        if (srow >= batchStart) {
            const float4* sp = (const float4*)(res_in + (size_t)srow * RCH + c2);
            float4 a = sp[0], b2 = sp[1];
            v[0]=a.x; v[1]=a.y; v[2]=a.z; v[3]=a.w; v[4]=b2.x; v[5]=b2.y; v[6]=b2.z; v[7]=b2.w;
        } else {
            #pragma unroll
            for (int q = 0; q < 8; q++) v[q] = 0.f;
        }
        uint4 hp, lp;
        uint32_t* hw = (uint32_t*)&hp;
        uint32_t* lw = (uint32_t*)&lp;
        #pragma unroll
        for (int q = 0; q < 4; q++) {
            __nv_bfloat16 h0 = __float2bfloat16(v[2*q]),   h1 = __float2bfloat16(v[2*q+1]);
            __nv_bfloat16 l0 = __float2bfloat16(v[2*q]   - __bfloat162float(h0));
            __nv_bfloat16 l1 = __float2bfloat16(v[2*q+1] - __bfloat162float(h1));
            hw[q] = (uint32_t)__bfloat16_as_ushort(h0) | ((uint32_t)__bfloat16_as_ushort(h1) << 16);
            lw[q] = (uint32_t)__bfloat16_as_ushort(l0) | ((uint32_t)__bfloat16_as_ushort(l1) << 16);
        }
        uint32_t dst = sA + row * SA_STRIDE + ch * 2;
        STS128(dst, hp);
        STS128(dst + ALO_OFF, lp);
    }
    __syncthreads();

    // ldmatrix lane addressing
    const int mbase = (wid & 1) * 32;
    const int nbase = (wid >> 1) * 32;
    const int aRow = lane & 15, aCol = (lane >> 4) * 8;
    const int bm = lane >> 3;
    const int bRow = (lane & 7) + ((bm >> 1) * 8), bCol = (bm & 1) * 8;
    const uint32_t aBase = sA + (mbase + aRow) * SA_STRIDE + aCol * 2;
    const uint32_t bB = sW + (nbase + bRow) * W_STRIDE + bCol * 2;

    const int qrow = lane >> 2, qcol = (lane & 3) * 2;

    float accf[2][4][4], accg[2][4][4];
    #pragma unroll
    for (int mt = 0; mt < 2; mt++)
        #pragma unroll
        for (int nq = 0; nq < 4; nq++)
            #pragma unroll
            for (int q = 0; q < 4; q++) { accf[mt][nq][q] = 0.f; accg[mt][nq][q] = 0.f; }

    // ---- fg: 16 tiles, double-buffered
    for (int t = 0; t < 16; t++) {
        if (t < 15) stage1(sW + ((t + 1) & 1) * W_TILE, FG_TILE(t + 1), tid);
        else        stage1(sW + ((t + 1) & 1) * W_TILE, SR_TILE(0), tid);
        CP_COMMIT();
        CP_WAIT_1();          // tile t resident
        __syncthreads();
        int c = t >> 2, gate = (t >> 1) & 1;
        uint32_t wb = (uint32_t)(t & 1) * W_TILE;
        if (t & 1) { if (gate) COMPUTE_LO(accg, c, wb); else COMPUTE_LO(accf, c, wb); }
        else       { if (gate) COMPUTE_HI(accg, c, wb); else COMPUTE_HI(accf, c, wb); }
        __syncthreads();
    }

    // ---- gate epilogue: p = tanh(f+fb)*sigmoid(g+gb) -> hi/lo into A buffer
    #pragma unroll
    for (int mt = 0; mt < 2; mt++)
        #pragma unroll
        for (int nq = 0; nq < 4; nq++)
            #pragma unroll
            for (int rp = 0; rp < 2; rp++) {
                int row = mbase + mt * 16 + qrow + rp * 8;
                int col = nbase + nq * 8 + qcol;
                float f0 = tanhf(accf[mt][nq][rp * 2]     + sbias[col]);
                float f1 = tanhf(accf[mt][nq][rp * 2 + 1] + sbias[col + 1]);
                float g0 = 1.f / (1.f + __expf(-(accg[mt][nq][rp * 2]     + sbias[128 + col])));
                float g1 = 1.f / (1.f + __expf(-(accg[mt][nq][rp * 2 + 1] + sbias[128 + col + 1])));
                float p0 = f0 * g0, p1 = f1 * g1;
                __nv_bfloat16 h0 = __float2bfloat16(p0), h1 = __float2bfloat16(p1);
                __nv_bfloat16 l0 = __float2bfloat16(p0 - __bfloat162float(h0));
                __nv_bfloat16 l1 = __float2bfloat16(p1 - __bfloat162float(h1));
                uint32_t hv = (uint32_t)__bfloat16_as_ushort(h0) | ((uint32_t)__bfloat16_as_ushort(h1) << 16);
                uint32_t lv = (uint32_t)__bfloat16_as_ushort(l0) | ((uint32_t)__bfloat16_as_ushort(l1) << 16);
                uint32_t dst = sA + row * SA_STRIDE + col * 2;
                STS32(dst, hv);
                STS32(dst + ALO_OFF, lv);
            }
    __syncthreads();

    // ---- sr: 8 tiles, double-buffered
    float accs[2][4][4], accr[2][4][4];
    #pragma unroll
    for (int mt = 0; mt < 2; mt++)
        #pragma unroll
        for (int nq = 0; nq < 4; nq++)
            #pragma unroll
            for (int q = 0; q < 4; q++) { accs[mt][nq][q] = 0.f; accr[mt][nq][q] = 0.f; }

    for (int u = 0; u < 8; u++) {
        if (u < 7) {
            stage1(sW + ((u + 1) & 1) * W_TILE, SR_TILE(u + 1), tid);
            CP_COMMIT();
            CP_WAIT_1();
        } else {
            CP_WAIT_0();
        }
        __syncthreads();
        int c = u >> 2, mat = (u >> 1) & 1;
        uint32_t wb = (uint32_t)(u & 1) * W_TILE;
        if (u & 1) { if (mat) COMPUTE_LO(accr, c, wb); else COMPUTE_LO(accs, c, wb); }
        else       { if (mat) COMPUTE_HI(accr, c, wb); else COMPUTE_HI(accs, c, wb); }
        __syncthreads();
    }

    // ---- final epilogue
    #pragma unroll
    for (int mt = 0; mt < 2; mt++)
        #pragma unroll
        for (int nq = 0; nq < 4; nq++)
            #pragma unroll
            for (int rp = 0; rp < 2; rp++) {
                int row = mbase + mt * 16 + qrow + rp * 8;
                int col = nbase + nq * 8 + qcol;
                int grow = row0 + row;
                float s0 = accs[mt][nq][rp * 2]     + sbias[256 + col];
                float s1 = accs[mt][nq][rp * 2 + 1] + sbias[256 + col + 1];
                float* oa = out_acc + (size_t)grow * RCH + col;
                if (!first) {
                    float2 oo = *(const float2*)oa;
                    s0 += oo.x; s1 += oo.y;
                }
                *(float2*)oa = make_float2(s0, s1);
                float2 rv = *(const float2*)(res_in + (size_t)grow * RCH + col);
                float r0 = rv.x + accr[mt][nq][rp * 2]     + sbias[384 + col];
                float r1 = rv.y + accr[mt][nq][rp * 2 + 1] + sbias[384 + col + 1];
                *(float2*)(res_out + (size_t)grow * RCH + col) = make_float2(r0, r1);
            }
    #undef FG_TILE
    #undef SR_TILE
}

// ---------------------------------------------------------------------------
// Initial causal conv: K=32, 64 -> 128, dilation 1.  128 thr, 8x8 tile. (SIMT)
__global__ void __launch_bounds__(128, 2) init_kernel(
    const float* __restrict__ X, const float* __restrict__ W,
    const float* __restrict__ B, float* __restrict__ res_out)
{
    extern __shared__ float sm[];
    float* xt = sm;
    float* wb = sm + 96 * 64;
    const int tid  = threadIdx.x;
    const int row0 = blockIdx.x * TM;
    const int batchStart = (row0 / T_LEN) * T_LEN;

    for (int i = tid; i < 95 * 16; i += NT) {
        int r = i >> 4, c4 = i & 15;
        int src = row0 - 31 + r;
        float4 v = make_float4(0.f, 0.f, 0.f, 0.f);
        if (src >= batchStart) v = ((const float4*)(X + (size_t)src * 64))[c4];
        ((float4*)(xt + r * 64))[c4] = v;
    }

    const int ty = tid >> 4, tx = tid & 15;
    const int r0 = ty * 8, c0 = tx * 8;

    ull acc[8][4];
    #pragma unroll
    for (int j = 0; j < 4; j++) {
        ull b = pk2(B[c0 + 2*j], B[c0 + 2*j + 1]);
        #pragma unroll
        for (int rr = 0; rr < 8; rr++) acc[rr][j] = b;
    }

    for (int j = 0; j < 32; j++) {
        __syncthreads();
        const float4* ws = (const float4*)(W + (size_t)j * 64 * 128);
        for (int i = tid; i < 2048; i += NT) ((float4*)wb)[i] = ws[i];
        __syncthreads();
        #pragma unroll 2
        for (int kk = 0; kk < 64; kk += 2) {
            float2 ap[8];
            #pragma unroll
            for (int rr = 0; rr < 8; rr++)
                ap[rr] = *(const float2*)(xt + (r0 + rr + j) * 64 + kk);
            #pragma unroll
            for (int q = 0; q < 2; q++) {
                const float* wp = wb + (kk + q) * 128 + c0;
                ulonglong2 wa = *(const ulonglong2*)wp;
                ulonglong2 wc = *(const ulonglong2*)(wp + 4);
                #pragma unroll
                for (int rr = 0; rr < 8; rr++) {
                    float a = q ? ap[rr].y : ap[rr].x;
                    ull ad = pk2(a, a);
                    fma2(acc[rr][0], ad, wa.x);
                    fma2(acc[rr][1], ad, wa.y);
                    fma2(acc[rr][2], ad, wc.x);
                    fma2(acc[rr][3], ad, wc.y);
                }
            }
        }
    }
    #pragma unroll
    for (int rr = 0; rr < 8; rr++) {
        float o[8];
        #pragma unroll
        for (int j = 0; j < 4; j++) upk2(acc[rr][j], o[2*j], o[2*j+1]);
        float* dst = res_out + (size_t)(row0 + r0 + rr) * RCH + c0;
        ((float4*)dst)[0] = make_float4(o[0], o[1], o[2], o[3]);
        ((float4*)dst)[1] = make_float4(o[4], o[5], o[6], o[7]);
    }
}

// ---------------------------------------------------------------------------
// Post chain: one warp handles TWO rows, packed lo/hi into f32x2 lanes. (SIMT)
__global__ void __launch_bounds__(256) post_kernel(
    const float* __restrict__ out_acc,
    const float* __restrict__ s0w, const float* __restrict__ s0b,
    const float* __restrict__ srw, const float* __restrict__ srb,
    const float* __restrict__ fnw, const float* __restrict__ fnb,
    float* __restrict__ y)
{
    extern __shared__ float sm[];
    float* w0 = sm;
    float* wr = w0 + 4096;
    float* wf = wr + 31744;
    float* b0 = wf + 8192;
    float* br = b0 + 32;
    float* bf = br + 992;

    const int tid = threadIdx.x;
    for (int i = tid; i < 4096;  i += blockDim.x) w0[i] = s0w[i];
    for (int i = tid; i < 31744; i += blockDim.x) wr[i] = srw[i];
    for (int i = tid; i < 8192;  i += blockDim.x) wf[i] = fnw[i];
    for (int i = tid; i < 32;    i += blockDim.x) b0[i] = s0b[i];
    for (int i = tid; i < 992;   i += blockDim.x) br[i] = srb[i];
    for (int i = tid; i < 256;   i += blockDim.x) bf[i] = fnb[i];
    __syncthreads();

    const int warp = tid >> 5, lane = tid & 31;
    const int nwarp = blockDim.x >> 5;

    for (int pr = blockIdx.x * nwarp + warp; pr < BT / 2; pr += gridDim.x * nwarp) {
        const int rowA = pr * 2, rowB = pr * 2 + 1;
        float4 xa = ((const float4*)(out_acc + (size_t)rowA * RCH))[lane];
        float4 xb = ((const float4*)(out_acc + (size_t)rowB * RCH))[lane];
        xa.x = fmaxf(xa.x, 0.f); xa.y = fmaxf(xa.y, 0.f); xa.z = fmaxf(xa.z, 0.f); xa.w = fmaxf(xa.w, 0.f);
        xb.x = fmaxf(xb.x, 0.f); xb.y = fmaxf(xb.y, 0.f); xb.z = fmaxf(xb.z, 0.f); xb.w = fmaxf(xb.w, 0.f);
        ull xp0 = pk2(xa.x, xb.x), xp1 = pk2(xa.y, xb.y);
        ull xp2 = pk2(xa.z, xb.z), xp3 = pk2(xa.w, xb.w);

        float bb = b0[lane];
        ull h = pk2(bb, bb);
        #pragma unroll
        for (int s = 0; s < 32; s++) {
            ull v0 = __shfl_sync(0xffffffffu, xp0, s);
            ull v1 = __shfl_sync(0xffffffffu, xp1, s);
            ull v2 = __shfl_sync(0xffffffffu, xp2, s);
            ull v3 = __shfl_sync(0xffffffffu, xp3, s);
            float wv0 = w0[(s*4+0)*32 + lane];
            float wv1 = w0[(s*4+1)*32 + lane];
            float wv2 = w0[(s*4+2)*32 + lane];
            float wv3 = w0[(s*4+3)*32 + lane];
            fma2(h, v0, pk2(wv0, wv0));
            fma2(h, v1, pk2(wv1, wv1));
            fma2(h, v2, pk2(wv2, wv2));
            fma2(h, v3, pk2(wv3, wv3));
        }
        for (int li = 0; li < 31; li++) {
            float hl, hh; upk2(h, hl, hh);
            ull rv = pk2(fmaxf(hl, 0.f), fmaxf(hh, 0.f));
            const float* wp = wr + li * 1024;
            float bl = br[li*32 + lane];
            ull ha = pk2(bl, bl);
            ull hb = pk2(0.f, 0.f);
            #pragma unroll
            for (int s = 0; s < 32; s += 2) {
                ull ra  = __shfl_sync(0xffffffffu, rv, s);
                ull rb2 = __shfl_sync(0xffffffffu, rv, s + 1);
                float wA = wp[(s    )*32 + lane];
                float wB = wp[(s + 1)*32 + lane];
                fma2(ha, ra,  pk2(wA, wA));
                fma2(hb, rb2, pk2(wB, wB));
            }
            h = add2(ha, hb);
        }
        float hl, hh; upk2(h, hl, hh);
        ull rv = pk2(fmaxf(hl, 0.f), fmaxf(hh, 0.f));
        ull accP[8];
        #pragma unroll
        for (int u = 0; u < 8; u++) {
            float b = bf[lane*8 + u];
            accP[u] = pk2(b, b);
        }
        #pragma unroll
        for (int s = 0; s < 32; s++) {
            ull rs = __shfl_sync(0xffffffffu, rv, s);
            const float* wp = wf + s*256 + lane*8;
            float4 wq0 = *(const float4*)wp;
            float4 wq1 = *(const float4*)(wp + 4);
            fma2(accP[0], rs, pk2(wq0.x, wq0.x));
            fma2(accP[1], rs, pk2(wq0.y, wq0.y));
            fma2(accP[2], rs, pk2(wq0.z, wq0.z));
            fma2(accP[3], rs, pk2(wq0.w, wq0.w));
            fma2(accP[4], rs, pk2(wq1.x, wq1.x));
            fma2(accP[5], rs, pk2(wq1.y, wq1.y));
            fma2(accP[6], rs, pk2(wq1.z, wq1.z));
            fma2(accP[7], rs, pk2(wq1.w, wq1.w));
        }
        float oa[8], ob[8];
        #pragma unroll
        for (int u = 0; u < 8; u++) upk2(accP[u], oa[u], ob[u]);
        float4* ya = (float4*)(y + (size_t)rowA * 256 + lane * 8);
        ya[0] = make_float4(oa[0], oa[1], oa[2], oa[3]);
        ya[1] = make_float4(oa[4], oa[5], oa[6], oa[7]);
        float4* yb = (float4*)(y + (size_t)rowB * 256 + lane * 8);
        yb[0] = make_float4(ob[0], ob[1], ob[2], ob[3]);
        yb[1] = make_float4(ob[4], ob[5], ob[6], ob[7]);
    }
}

// ---------------------------------------------------------------------------
extern "C" void kernel_launch(void* const* d_in, const int* in_sizes, int n_in,
                              void* d_out, int out_size)
{
    const float* X       = (const float*)d_in[0];
    const float* init_w  = (const float*)d_in[1];
    const float* init_b  = (const float*)d_in[2];
    const float* f_w     = (const float*)d_in[3];
    const float* f_b     = (const float*)d_in[4];
    const float* g_w     = (const float*)d_in[5];
    const float* g_b     = (const float*)d_in[6];
    const float* skip_w  = (const float*)d_in[7];
    const float* skip_b  = (const float*)d_in[8];
    const float* res_w   = (const float*)d_in[9];
    const float* res_b   = (const float*)d_in[10];
    const float* skip0_w = (const float*)d_in[11];
    const float* skip0_b = (const float*)d_in[12];
    const float* skipr_w = (const float*)d_in[13];
    const float* skipr_b = (const float*)d_in[14];
    const float* final_w = (const float*)d_in[15];
    const float* final_b = (const float*)d_in[16];
    float* y = (float*)d_out;

    float *resA, *resB, *outacc;
    __nv_bfloat16 *wfg, *wsr;
    cudaGetSymbolAddress((void**)&resA,   g_resA);
    cudaGetSymbolAddress((void**)&resB,   g_resB);
    cudaGetSymbolAddress((void**)&outacc, g_outacc);
    cudaGetSymbolAddress((void**)&wfg,    g_wfg);
    cudaGetSymbolAddress((void**)&wsr,    g_wsr);

    const int INIT_SMEM  = (96*64 + 64*128) * 4;
    const int POST_SMEM  = (4096 + 31744 + 8192 + 32 + 992 + 256) * 4;
    cudaFuncSetAttribute(init_kernel,   cudaFuncAttributeMaxDynamicSharedMemorySize, INIT_SMEM);
    cudaFuncSetAttribute(tlayer_kernel, cudaFuncAttributeMaxDynamicSharedMemorySize, LSMEM);
    cudaFuncSetAttribute(post_kernel,   cudaFuncAttributeMaxDynamicSharedMemorySize, POST_SMEM);

    prep_kernel<<<2048, 256>>>(f_w, g_w, skip_w, res_w);
    init_kernel<<<BT / TM, NT, INIT_SMEM>>>(X, init_w, init_b, resA);

    static const int DIL[20] = {1,2,4,8,16,32,64,128,256,512,
                                1,2,4,8,16,32,64,128,256,512};
    for (int i = 0; i < 20; i++) {
        const float* rin  = (i & 1) ? resB : resA;
        float*       rout = (i & 1) ? resA : resB;
        tlayer_kernel<<<BT / TM, 256, LSMEM>>>(
            rin, rout, outacc,
            wfg + (size_t)i * 16 * 8192, wsr + (size_t)i * 8 * 8192,
            f_b + i * RCH, g_b + i * RCH, skip_b + i * RCH, res_b + i * RCH,
            DIL[i], (i == 0) ? 1 : 0);
    }

    post_kernel<<<1184, 256, POST_SMEM>>>(outacc, skip0_w, skip0_b,
                                          skipr_w, skipr_b, final_w, final_b, y);
}

// round 15
// speedup vs baseline: 1.0423x; 1.0423x over previous
#include <cuda_runtime.h>
#include <cuda_bf16.h>
#include <math.h>
#include <stdint.h>

typedef unsigned long long ull;

#define BT    65536
#define T_LEN 16384
#define RCH   128
#define TM    64
#define NT    128

// ---------------- scratch ---------------------------------------------------
__device__ float g_resA[BT * RCH];
__device__ float g_resB[BT * RCH];
__device__ float g_outacc[BT * RCH];
__device__ __nv_bfloat16 g_wfg[20 * 16 * 8192];
__device__ __nv_bfloat16 g_wsr[20 * 8 * 8192];

// ---------------- packed f32x2 helpers --------------------------------------
__device__ __forceinline__ ull pk2(float lo, float hi) {
    ull r; asm("mov.b64 %0, {%1, %2};" : "=l"(r) : "f"(lo), "f"(hi)); return r;
}
__device__ __forceinline__ void upk2(ull v, float& lo, float& hi) {
    asm("mov.b64 {%0, %1}, %2;" : "=f"(lo), "=f"(hi) : "l"(v));
}
__device__ __forceinline__ void fma2(ull& d, ull a, ull b) {
    asm("fma.rn.f32x2 %0, %1, %2, %0;" : "+l"(d) : "l"(a), "l"(b));
}
__device__ __forceinline__ ull add2(ull a, ull b) {
    ull r; asm("add.rn.f32x2 %0, %1, %2;" : "=l"(r) : "l"(a), "l"(b)); return r;
}

// ---------------- warp-mma helpers ------------------------------------------
__device__ __forceinline__ uint32_t s2u(const void* p) {
    uint32_t a;
    asm("{ .reg .u64 t; cvta.to.shared.u64 t, %1; cvt.u32.u64 %0, t; }" : "=r"(a) : "l"(p));
    return a;
}
__device__ __forceinline__ void ldm4(uint32_t* r, uint32_t addr) {
    asm volatile("ldmatrix.sync.aligned.m8n8.x4.shared.b16 {%0,%1,%2,%3}, [%4];"
                 : "=r"(r[0]), "=r"(r[1]), "=r"(r[2]), "=r"(r[3]) : "r"(addr));
}
__device__ __forceinline__ void mma16816(float* d, const uint32_t* a, uint32_t b0, uint32_t b1) {
    asm volatile("mma.sync.aligned.m16n8k16.row.col.f32.bf16.bf16.f32 "
                 "{%0,%1,%2,%3}, {%4,%5,%6,%7}, {%8,%9}, {%0,%1,%2,%3};"
                 : "+f"(d[0]), "+f"(d[1]), "+f"(d[2]), "+f"(d[3])
                 : "r"(a[0]), "r"(a[1]), "r"(a[2]), "r"(a[3]), "r"(b0), "r"(b1));
}
#define STS128(a, v) \
    asm volatile("st.shared.v4.b32 [%0], {%1,%2,%3,%4};" :: "r"(a), "r"((v).x), "r"((v).y), "r"((v).z), "r"((v).w))
#define STS32(a, v) asm volatile("st.shared.b32 [%0], %1;" :: "r"(a), "r"(v))
#define CP_ASYNC16(d, s) asm volatile("cp.async.cg.shared.global [%0], [%1], 16;" :: "r"(d), "l"(s))
#define CP_COMMIT()      asm volatile("cp.async.commit_group;" ::: "memory")
#define CP_WAIT_ALL()    asm volatile("cp.async.wait_all;" ::: "memory")
#define CP_WAIT_1()      asm volatile("cp.async.wait_group 1;" ::: "memory")
#define CP_WAIT_0()      asm volatile("cp.async.wait_group 0;" ::: "memory")

// smem layout (bytes): bias[512 f32] | A hi [64x264 bf16] | A lo | W: 1 buffer x 2 tiles
#define SA_STRIDE 528
#define ALO_OFF   33792
#define W_STRIDE  144
#define W_TILE    18432
#define OFF_A     2048
#define OFF_W     (OFF_A + 2 * 33792)     // 69632
#define LSMEM     (OFF_W + 2 * W_TILE)    // 106496  -> 2 CTAs/SM

// ---------------------------------------------------------------------------
// Weight prep: split fp32 weights to bf16 hi/lo, transpose to [n][k] tiles.
__global__ void prep_kernel(const float* __restrict__ fw, const float* __restrict__ gw,
                            const float* __restrict__ sw, const float* __restrict__ rw)
{
    const int total_fg = 20 * 2 * 4 * 128 * 64;
    const int total_sr = 20 * 2 * 2 * 128 * 64;
    for (int idx = blockIdx.x * blockDim.x + threadIdx.x; idx < total_fg + total_sr;
         idx += gridDim.x * blockDim.x) {
        if (idx < total_fg) {
            int k = idx & 63, n = (idx >> 6) & 127, c = (idx >> 13) & 3;
            int gate = (idx >> 15) & 1, layer = idx >> 16;
            int kk = c * 64 + k, tap = kk >> 7, kc = kk & 127;
            const float* src = gate ? gw : fw;
            float w = src[(((size_t)layer * 2 + tap) * 128 + kc) * 128 + n];
            __nv_bfloat16 hi = __float2bfloat16(w);
            __nv_bfloat16 lo = __float2bfloat16(w - __bfloat162float(hi));
            size_t tbase = ((size_t)layer * 16 + gate * 8) * 8192 + (size_t)n * 64 + k;
            g_wfg[tbase + (size_t)(0 * 4 + c) * 8192] = hi;
            g_wfg[tbase + (size_t)(1 * 4 + c) * 8192] = lo;
        } else {
            int j = idx - total_fg;
            int k = j & 63, n = (j >> 6) & 127, c = (j >> 13) & 1;
            int mat = (j >> 14) & 1, layer = j >> 15;
            int kc = c * 64 + k;
            const float* src = mat ? rw : sw;
            float w = src[((size_t)layer * 128 + kc) * 128 + n];
            __nv_bfloat16 hi = __float2bfloat16(w);
            __nv_bfloat16 lo = __float2bfloat16(w - __bfloat162float(hi));
            size_t tbase = ((size_t)layer * 8 + mat * 4) * 8192 + (size_t)n * 64 + k;
            g_wsr[tbase + (size_t)(0 * 2 + c) * 8192] = hi;
            g_wsr[tbase + (size_t)(1 * 2 + c) * 8192] = lo;
        }
    }
}

// stage one phase's weights (hi tile + lo tile) into the W buffer via cp.async
__device__ __forceinline__ void stage2(uint32_t dst, const __nv_bfloat16* __restrict__ hi,
                                       const __nv_bfloat16* __restrict__ lo, int tid)
{
    #pragma unroll
    for (int r = 0; r < 8; r++) {
        int i = r * 256 + tid;
        int t = i >> 10, u = i & 1023, n = u >> 3, ku = u & 7;
        const __nv_bfloat16* s = (t ? lo : hi) + (size_t)n * 64 + ku * 8;
        CP_ASYNC16(dst + t * W_TILE + n * W_STRIDE + ku * 16, s);
    }
}

// one phase of MMAs: acc += A(hi,lo) x W(hi,lo) over k-chunk cc
#define COMPUTE_PHASE(ACC, cc) do {                                            \
    _Pragma("unroll")                                                          \
    for (int ks = 0; ks < 4; ks++) {                                           \
        const int kA2 = ((cc) * 64 + ks * 16) * 2, kW2 = ks * 32;              \
        uint32_t ah[2][4], al[2][4], bh[2][4], bl[2][4];                       \
        ldm4(ah[0], aBase + kA2);                                              \
        ldm4(ah[1], aBase + 16 * SA_STRIDE + kA2);                             \
        ldm4(al[0], aBase + ALO_OFF + kA2);                                    \
        ldm4(al[1], aBase + ALO_OFF + 16 * SA_STRIDE + kA2);                   \
        ldm4(bh[0], bB + kW2);                                                 \
        ldm4(bh[1], bB + 16 * W_STRIDE + kW2);                                 \
        ldm4(bl[0], bB + W_TILE + kW2);                                        \
        ldm4(bl[1], bB + W_TILE + 16 * W_STRIDE + kW2);                        \
        _Pragma("unroll")                                                      \
        for (int mt = 0; mt < 2; mt++)                                         \
            _Pragma("unroll")                                                  \
            for (int nq = 0; nq < 4; nq++) {                                   \
                int nt = nq >> 1, pr = (nq & 1) * 2;                           \
                mma16816(ACC[mt][nq], ah[mt], bh[nt][pr], bh[nt][pr + 1]);     \
                mma16816(ACC[mt][nq], ah[mt], bl[nt][pr], bl[nt][pr + 1]);     \
                mma16816(ACC[mt][nq], al[mt], bh[nt][pr], bh[nt][pr + 1]);     \
            }                                                                  \
    }                                                                          \
} while (0)

// ---------------------------------------------------------------------------
// Tensor-core WaveNet layer (R12 structure: single W buffer, 2 CTAs/SM).
__global__ void __launch_bounds__(256, 2) tlayer_kernel(
    const float* __restrict__ res_in, float* __restrict__ res_out,
    float* __restrict__ out_acc,
    const __nv_bfloat16* __restrict__ wfg, const __nv_bfloat16* __restrict__ wsr,
    const float* __restrict__ fb, const float* __restrict__ gb,
    const float* __restrict__ sb, const float* __restrict__ rb,
    int d, int first)
{
    extern __shared__ char smem[];
    float* sbias = (float*)smem;
    const uint32_t sbase = s2u(smem);
    const uint32_t sA = sbase + OFF_A;
    const uint32_t sW = sbase + OFF_W;

    const int tid = threadIdx.x, wid = tid >> 5, lane = tid & 31;
    const int row0 = blockIdx.x * TM;
    const int batchStart = (row0 / T_LEN) * T_LEN;

    // prefetch phase-0 weights (f, chunk 0) while we stage A
    stage2(sW, wfg, wfg + (size_t)4 * 8192, tid);
    CP_COMMIT();

    for (int i = tid; i < 512; i += 256) {
        int grp = i >> 7, n = i & 127;
        const float* p = grp == 0 ? fb : grp == 1 ? gb : grp == 2 ? sb : rb;
        sbias[i] = p[n];
    }

    // ---- stage A = [prev(128) | cur(128)] as bf16 hi/lo, row-major [64][264]
    for (int idx = tid; idx < 2048; idx += 256) {
        int row = idx >> 5, ch = (idx & 31) * 8;
        int srow, c2;
        if (ch < 128) { srow = row0 + row - d; c2 = ch; }
        else          { srow = row0 + row;     c2 = ch - 128; }
        float v[8];
        if (srow >= batchStart) {
            const float4* sp = (const float4*)(res_in + (size_t)srow * RCH + c2);
            float4 a = sp[0], b2 = sp[1];
            v[0]=a.x; v[1]=a.y; v[2]=a.z; v[3]=a.w; v[4]=b2.x; v[5]=b2.y; v[6]=b2.z; v[7]=b2.w;
        } else {
            #pragma unroll
            for (int q = 0; q < 8; q++) v[q] = 0.f;
        }
        uint4 hp, lp;
        uint32_t* hw = (uint32_t*)&hp;
        uint32_t* lw = (uint32_t*)&lp;
        #pragma unroll
        for (int q = 0; q < 4; q++) {
            __nv_bfloat16 h0 = __float2bfloat16(v[2*q]),   h1 = __float2bfloat16(v[2*q+1]);
            __nv_bfloat16 l0 = __float2bfloat16(v[2*q]   - __bfloat162float(h0));
            __nv_bfloat16 l1 = __float2bfloat16(v[2*q+1] - __bfloat162float(h1));
            hw[q] = (uint32_t)__bfloat16_as_ushort(h0) | ((uint32_t)__bfloat16_as_ushort(h1) << 16);
            lw[q] = (uint32_t)__bfloat16_as_ushort(l0) | ((uint32_t)__bfloat16_as_ushort(l1) << 16);
        }
        uint32_t dst = sA + row * SA_STRIDE + ch * 2;
        STS128(dst, hp);
        STS128(dst + ALO_OFF, lp);
    }
    CP_WAIT_ALL();
    __syncthreads();

    // ldmatrix lane addressing
    const int mbase = (wid & 1) * 32;
    const int nbase = (wid >> 1) * 32;
    const int aRow = lane & 15, aCol = (lane >> 4) * 8;
    const int bm = lane >> 3;
    const int bRow = (lane & 7) + ((bm >> 1) * 8), bCol = (bm & 1) * 8;
    const uint32_t aBase = sA + (mbase + aRow) * SA_STRIDE + aCol * 2;
    const uint32_t bB = sW + (nbase + bRow) * W_STRIDE + bCol * 2;

    const int qrow = lane >> 2, qcol = (lane & 3) * 2;

    // ---- f/g: 8 phases (gate = p&1, chunk = p>>1); single W buffer
    {
        float accf[2][4][4], accg[2][4][4];
        #pragma unroll
        for (int mt = 0; mt < 2; mt++)
            #pragma unroll
            for (int nq = 0; nq < 4; nq++)
                #pragma unroll
                for (int q = 0; q < 4; q++) { accf[mt][nq][q] = 0.f; accg[mt][nq][q] = 0.f; }

        for (int p = 0; p < 8; p++) {
            int c = p >> 1;
            if (p & 1) COMPUTE_PHASE(accg, c);
            else       COMPUTE_PHASE(accf, c);
            __syncthreads();            // all warps done reading W
            if (p < 7) {
                int pn = p + 1, cn = pn >> 1, gate = pn & 1;
                stage2(sW, wfg + (size_t)(gate * 8 + cn) * 8192,
                           wfg + (size_t)(gate * 8 + 4 + cn) * 8192, tid);
            } else {
                stage2(sW, wsr, wsr + (size_t)2 * 8192, tid);   // sr phase 0
            }
            CP_COMMIT();
            CP_WAIT_ALL();
            __syncthreads();            // W ready (also: A reads done before epilogue)
        }

        // ---- gate epilogue: p = tanh(f+fb)*sigmoid(g+gb) -> hi/lo into A buffer
        #pragma unroll
        for (int mt = 0; mt < 2; mt++)
            #pragma unroll
            for (int nq = 0; nq < 4; nq++)
                #pragma unroll
                for (int rp = 0; rp < 2; rp++) {
                    int row = mbase + mt * 16 + qrow + rp * 8;
                    int col = nbase + nq * 8 + qcol;
                    float f0 = tanhf(accf[mt][nq][rp * 2]     + sbias[col]);
                    float f1 = tanhf(accf[mt][nq][rp * 2 + 1] + sbias[col + 1]);
                    float g0 = 1.f / (1.f + __expf(-(accg[mt][nq][rp * 2]     + sbias[128 + col])));
                    float g1 = 1.f / (1.f + __expf(-(accg[mt][nq][rp * 2 + 1] + sbias[128 + col + 1])));
                    float p0 = f0 * g0, p1 = f1 * g1;
                    __nv_bfloat16 h0 = __float2bfloat16(p0), h1 = __float2bfloat16(p1);
                    __nv_bfloat16 l0 = __float2bfloat16(p0 - __bfloat162float(h0));
                    __nv_bfloat16 l1 = __float2bfloat16(p1 - __bfloat162float(h1));
                    uint32_t hv = (uint32_t)__bfloat16_as_ushort(h0) | ((uint32_t)__bfloat16_as_ushort(h1) << 16);
                    uint32_t lv = (uint32_t)__bfloat16_as_ushort(l0) | ((uint32_t)__bfloat16_as_ushort(l1) << 16);
                    uint32_t dst = sA + row * SA_STRIDE + col * 2;
                    STS32(dst, hv);
                    STS32(dst + ALO_OFF, lv);
                }
    }
    __syncthreads();

    // ---- skip/res: 4 phases (skip c0, res c0, skip c1, res c1)
    float accs[2][4][4], accr[2][4][4];
    #pragma unroll
    for (int mt = 0; mt < 2; mt++)
        #pragma unroll
        for (int nq = 0; nq < 4; nq++)
            #pragma unroll
            for (int q = 0; q < 4; q++) { accs[mt][nq][q] = 0.f; accr[mt][nq][q] = 0.f; }

    for (int q = 0; q < 4; q++) {
        int c = q >> 1;
        if (q & 1) COMPUTE_PHASE(accr, c);
        else       COMPUTE_PHASE(accs, c);
        if (q < 3) {
            __syncthreads();
            int qn = q + 1, mat = qn & 1, cn = qn >> 1;
            stage2(sW, wsr + (size_t)(mat * 4 + cn) * 8192,
                       wsr + (size_t)(mat * 4 + 2 + cn) * 8192, tid);
            CP_COMMIT();
            CP_WAIT_ALL();
            __syncthreads();
        }
    }

    // ---- final epilogue
    #pragma unroll
    for (int mt = 0; mt < 2; mt++)
        #pragma unroll
        for (int nq = 0; nq < 4; nq++)
            #pragma unroll
            for (int rp = 0; rp < 2; rp++) {
                int row = mbase + mt * 16 + qrow + rp * 8;
                int col = nbase + nq * 8 + qcol;
                int grow = row0 + row;
                float s0 = accs[mt][nq][rp * 2]     + sbias[256 + col];
                float s1 = accs[mt][nq][rp * 2 + 1] + sbias[256 + col + 1];
                float* oa = out_acc + (size_t)grow * RCH + col;
                if (!first) {
                    float2 oo = *(const float2*)oa;
                    s0 += oo.x; s1 += oo.y;
                }
                *(float2*)oa = make_float2(s0, s1);
                float2 rv = *(const float2*)(res_in + (size_t)grow * RCH + col);
                float r0 = rv.x + accr[mt][nq][rp * 2]     + sbias[384 + col];
                float r1 = rv.y + accr[mt][nq][rp * 2 + 1] + sbias[384 + col + 1];
                *(float2*)(res_out + (size_t)grow * RCH + col) = make_float2(r0, r1);
            }
}

// ---------------------------------------------------------------------------
// Initial causal conv: K=32, 64 -> 128, dilation 1.  128 thr, 8x8 tile.
// cp.async double-buffered tap weight staging.
#define INIT_XT_F   (95 * 64)             // 6080 floats
#define INIT_WB_OFF (INIT_XT_F * 4)       // byte offset of weight buffers
#define INIT_SMEM   ((INIT_XT_F + 2 * 8192) * 4)   // 89856 B -> 2 blocks/SM

__global__ void __launch_bounds__(128, 2) init_kernel(
    const float* __restrict__ X, const float* __restrict__ W,
    const float* __restrict__ B, float* __restrict__ res_out)
{
    extern __shared__ float sm[];
    float* xt = sm;
    float* wb = sm + INIT_XT_F;           // two 8192-float buffers
    const uint32_t wb32 = s2u(sm) + INIT_WB_OFF;
    const int tid  = threadIdx.x;
    const int row0 = blockIdx.x * TM;
    const int batchStart = (row0 / T_LEN) * T_LEN;

    // prefetch tap 0 weights
    #pragma unroll
    for (int r = 0; r < 16; r++) {
        int i = r * 128 + tid;
        CP_ASYNC16(wb32 + i * 16, W + (size_t)i * 4);
    }
    CP_COMMIT();

    for (int i = tid; i < 95 * 16; i += NT) {
        int r = i >> 4, c4 = i & 15;
        int src = row0 - 31 + r;
        float4 v = make_float4(0.f, 0.f, 0.f, 0.f);
        if (src >= batchStart) v = ((const float4*)(X + (size_t)src * 64))[c4];
        ((float4*)(xt + r * 64))[c4] = v;
    }

    const int ty = tid >> 4, tx = tid & 15;
    const int r0 = ty * 8, c0 = tx * 8;

    ull acc[8][4];
    #pragma unroll
    for (int j = 0; j < 4; j++) {
        ull b = pk2(B[c0 + 2*j], B[c0 + 2*j + 1]);
        #pragma unroll
        for (int rr = 0; rr < 8; rr++) acc[rr][j] = b;
    }

    for (int j = 0; j < 32; j++) {
        if (j < 31) {
            const float* ws = W + (size_t)(j + 1) * 8192;
            uint32_t dst = wb32 + (uint32_t)(((j + 1) & 1) ? 32768 : 0);
            #pragma unroll
            for (int r = 0; r < 16; r++) {
                int i = r * 128 + tid;
                CP_ASYNC16(dst + i * 16, ws + (size_t)i * 4);
            }
            CP_COMMIT();
            CP_WAIT_1();
        } else {
            CP_WAIT_0();
        }
        __syncthreads();
        const float* wcur = wb + (j & 1) * 8192;
        #pragma unroll 2
        for (int kk = 0; kk < 64; kk += 2) {
            float2 ap[8];
            #pragma unroll
            for (int rr = 0; rr < 8; rr++)
                ap[rr] = *(const float2*)(xt + (r0 + rr + j) * 64 + kk);
            #pragma unroll
            for (int q = 0; q < 2; q++) {
                const float* wp = wcur + (kk + q) * 128 + c0;
                ulonglong2 wa = *(const ulonglong2*)wp;
                ulonglong2 wc = *(const ulonglong2*)(wp + 4);
                #pragma unroll
                for (int rr = 0; rr < 8; rr++) {
                    float a = q ? ap[rr].y : ap[rr].x;
                    ull ad = pk2(a, a);
                    fma2(acc[rr][0], ad, wa.x);
                    fma2(acc[rr][1], ad, wa.y);
                    fma2(acc[rr][2], ad, wc.x);
                    fma2(acc[rr][3], ad, wc.y);
                }
            }
        }
        __syncthreads();
    }
    #pragma unroll
    for (int rr = 0; rr < 8; rr++) {
        float o[8];
        #pragma unroll
        for (int j = 0; j < 4; j++) upk2(acc[rr][j], o[2*j], o[2*j+1]);
        float* dst = res_out + (size_t)(row0 + r0 + rr) * RCH + c0;
        ((float4*)dst)[0] = make_float4(o[0], o[1], o[2], o[3]);
        ((float4*)dst)[1] = make_float4(o[4], o[5], o[6], o[7]);
    }
}

// ---------------------------------------------------------------------------
// Post chain: 1024 threads/block (32 warps/SM) to hide the serial shfl chain.
__global__ void __launch_bounds__(1024) post_kernel(
    const float* __restrict__ out_acc,
    const float* __restrict__ s0w, const float* __restrict__ s0b,
    const float* __restrict__ srw, const float* __restrict__ srb,
    const float* __restrict__ fnw, const float* __restrict__ fnb,
    float* __restrict__ y)
{
    extern __shared__ float sm[];
    float* w0 = sm;
    float* wr = w0 + 4096;
    float* wf = wr + 31744;
    float* b0 = wf + 8192;
    float* br = b0 + 32;
    float* bf = br + 992;

    const int tid = threadIdx.x;
    for (int i = tid; i < 4096;  i += blockDim.x) w0[i] = s0w[i];
    for (int i = tid; i < 31744; i += blockDim.x) wr[i] = srw[i];
    for (int i = tid; i < 8192;  i += blockDim.x) wf[i] = fnw[i];
    for (int i = tid; i < 32;    i += blockDim.x) b0[i] = s0b[i];
    for (int i = tid; i < 992;   i += blockDim.x) br[i] = srb[i];
    for (int i = tid; i < 256;   i += blockDim.x) bf[i] = fnb[i];
    __syncthreads();

    const int warp = tid >> 5, lane = tid & 31;
    const int nwarp = blockDim.x >> 5;

    for (int pr = blockIdx.x * nwarp + warp; pr < BT / 2; pr += gridDim.x * nwarp) {
        const int rowA = pr * 2, rowB = pr * 2 + 1;
        float4 xa = ((const float4*)(out_acc + (size_t)rowA * RCH))[lane];
        float4 xb = ((const float4*)(out_acc + (size_t)rowB * RCH))[lane];
        xa.x = fmaxf(xa.x, 0.f); xa.y = fmaxf(xa.y, 0.f); xa.z = fmaxf(xa.z, 0.f); xa.w = fmaxf(xa.w, 0.f);
        xb.x = fmaxf(xb.x, 0.f); xb.y = fmaxf(xb.y, 0.f); xb.z = fmaxf(xb.z, 0.f); xb.w = fmaxf(xb.w, 0.f);
        ull xp0 = pk2(xa.x, xb.x), xp1 = pk2(xa.y, xb.y);
        ull xp2 = pk2(xa.z, xb.z), xp3 = pk2(xa.w, xb.w);

        float bb = b0[lane];
        ull h = pk2(bb, bb);
        #pragma unroll
        for (int s = 0; s < 32; s++) {
            ull v0 = __shfl_sync(0xffffffffu, xp0, s);
            ull v1 = __shfl_sync(0xffffffffu, xp1, s);
            ull v2 = __shfl_sync(0xffffffffu, xp2, s);
            ull v3 = __shfl_sync(0xffffffffu, xp3, s);
            float wv0 = w0[(s*4+0)*32 + lane];
            float wv1 = w0[(s*4+1)*32 + lane];
            float wv2 = w0[(s*4+2)*32 + lane];
            float wv3 = w0[(s*4+3)*32 + lane];
            fma2(h, v0, pk2(wv0, wv0));
            fma2(h, v1, pk2(wv1, wv1));
            fma2(h, v2, pk2(wv2, wv2));
            fma2(h, v3, pk2(wv3, wv3));
        }
        for (int li = 0; li < 31; li++) {
            float hl, hh; upk2(h, hl, hh);
            ull rv = pk2(fmaxf(hl, 0.f), fmaxf(hh, 0.f));
            const float* wp = wr + li * 1024;
            float bl = br[li*32 + lane];
            ull ha = pk2(bl, bl);
            ull hb = pk2(0.f, 0.f);
            #pragma unroll
            for (int s = 0; s < 32; s += 2) {
                ull ra  = __shfl_sync(0xffffffffu, rv, s);
                ull rb2 = __shfl_sync(0xffffffffu, rv, s + 1);
                float wA = wp[(s    )*32 + lane];
                float wB = wp[(s + 1)*32 + lane];
                fma2(ha, ra,  pk2(wA, wA));
                fma2(hb, rb2, pk2(wB, wB));
            }
            h = add2(ha, hb);
        }
        float hl, hh; upk2(h, hl, hh);
        ull rv = pk2(fmaxf(hl, 0.f), fmaxf(hh, 0.f));
        ull accP[8];
        #pragma unroll
        for (int u = 0; u < 8; u++) {
            float b = bf[lane*8 + u];
            accP[u] = pk2(b, b);
        }
        #pragma unroll
        for (int s = 0; s < 32; s++) {
            ull rs = __shfl_sync(0xffffffffu, rv, s);
            const float* wp = wf + s*256 + lane*8;
            float4 wq0 = *(const float4*)wp;
            float4 wq1 = *(const float4*)(wp + 4);
            fma2(accP[0], rs, pk2(wq0.x, wq0.x));
            fma2(accP[1], rs, pk2(wq0.y, wq0.y));
            fma2(accP[2], rs, pk2(wq0.z, wq0.z));
            fma2(accP[3], rs, pk2(wq0.w, wq0.w));
            fma2(accP[4], rs, pk2(wq1.x, wq1.x));
            fma2(accP[5], rs, pk2(wq1.y, wq1.y));
            fma2(accP[6], rs, pk2(wq1.z, wq1.z));
            fma2(accP[7], rs, pk2(wq1.w, wq1.w));
        }
        float oa[8], ob[8];
        #pragma unroll
        for (int u = 0; u < 8; u++) upk2(accP[u], oa[u], ob[u]);
        float4* ya = (float4*)(y + (size_t)rowA * 256 + lane * 8);
        ya[0] = make_float4(oa[0], oa[1], oa[2], oa[3]);
        ya[1] = make_float4(oa[4], oa[5], oa[6], oa[7]);
        float4* yb = (float4*)(y + (size_t)rowB * 256 + lane * 8);
        yb[0] = make_float4(ob[0], ob[1], ob[2], ob[3]);
        yb[1] = make_float4(ob[4], ob[5], ob[6], ob[7]);
    }
}

// ---------------------------------------------------------------------------
extern "C" void kernel_launch(void* const* d_in, const int* in_sizes, int n_in,
                              void* d_out, int out_size)
{
    const float* X       = (const float*)d_in[0];
    const float* init_w  = (const float*)d_in[1];
    const float* init_b  = (const float*)d_in[2];
    const float* f_w     = (const float*)d_in[3];
    const float* f_b     = (const float*)d_in[4];
    const float* g_w     = (const float*)d_in[5];
    const float* g_b     = (const float*)d_in[6];
    const float* skip_w  = (const float*)d_in[7];
    const float* skip_b  = (const float*)d_in[8];
    const float* res_w   = (const float*)d_in[9];
    const float* res_b   = (const float*)d_in[10];
    const float* skip0_w = (const float*)d_in[11];
    const float* skip0_b = (const float*)d_in[12];
    const float* skipr_w = (const float*)d_in[13];
    const float* skipr_b = (const float*)d_in[14];
    const float* final_w = (const float*)d_in[15];
    const float* final_b = (const float*)d_in[16];
    float* y = (float*)d_out;

    float *resA, *resB, *outacc;
    __nv_bfloat16 *wfg, *wsr;
    cudaGetSymbolAddress((void**)&resA,   g_resA);
    cudaGetSymbolAddress((void**)&resB,   g_resB);
    cudaGetSymbolAddress((void**)&outacc, g_outacc);
    cudaGetSymbolAddress((void**)&wfg,    g_wfg);
    cudaGetSymbolAddress((void**)&wsr,    g_wsr);

    const int POST_SMEM = (4096 + 31744 + 8192 + 32 + 992 + 256) * 4;
    cudaFuncSetAttribute(init_kernel,   cudaFuncAttributeMaxDynamicSharedMemorySize, INIT_SMEM);
    cudaFuncSetAttribute(tlayer_kernel, cudaFuncAttributeMaxDynamicSharedMemorySize, LSMEM);
    cudaFuncSetAttribute(post_kernel,   cudaFuncAttributeMaxDynamicSharedMemorySize, POST_SMEM);

    prep_kernel<<<2048, 256>>>(f_w, g_w, skip_w, res_w);
    init_kernel<<<BT / TM, NT, INIT_SMEM>>>(X, init_w, init_b, resA);

    static const int DIL[20] = {1,2,4,8,16,32,64,128,256,512,
                                1,2,4,8,16,32,64,128,256,512};
    for (int i = 0; i < 20; i++) {
        const float* rin  = (i & 1) ? resB : resA;
        float*       rout = (i & 1) ? resA : resB;
        tlayer_kernel<<<BT / TM, 256, LSMEM>>>(
            rin, rout, outacc,
            wfg + (size_t)i * 16 * 8192, wsr + (size_t)i * 8 * 8192,
            f_b + i * RCH, g_b + i * RCH, skip_b + i * RCH, res_b + i * RCH,
            DIL[i], (i == 0) ? 1 : 0);
    }

    post_kernel<<<296, 1024, POST_SMEM>>>(outacc, skip0_w, skip0_b,
                                          skipr_w, skipr_b, final_w, final_b, y);
}

// round 16
// speedup vs baseline: 1.0432x; 1.0009x over previous
#include <cuda_runtime.h>
#include <cuda_bf16.h>
#include <math.h>
#include <stdint.h>

typedef unsigned long long ull;

#define BT    65536
#define T_LEN 16384
#define RCH   128
#define TM    64
#define NT    128

// ---------------- scratch ---------------------------------------------------
__device__ float g_resA[BT * RCH];
__device__ float g_resB[BT * RCH];
__device__ float g_outacc[BT * RCH];
__device__ __nv_bfloat16 g_wfg[20 * 16 * 8192];
__device__ __nv_bfloat16 g_wsr[20 * 8 * 8192];

// ---------------- packed f32x2 helpers --------------------------------------
__device__ __forceinline__ ull pk2(float lo, float hi) {
    ull r; asm("mov.b64 %0, {%1, %2};" : "=l"(r) : "f"(lo), "f"(hi)); return r;
}
__device__ __forceinline__ void upk2(ull v, float& lo, float& hi) {
    asm("mov.b64 {%0, %1}, %2;" : "=f"(lo), "=f"(hi) : "l"(v));
}
__device__ __forceinline__ void fma2(ull& d, ull a, ull b) {
    asm("fma.rn.f32x2 %0, %1, %2, %0;" : "+l"(d) : "l"(a), "l"(b));
}
__device__ __forceinline__ ull add2(ull a, ull b) {
    ull r; asm("add.rn.f32x2 %0, %1, %2;" : "=l"(r) : "l"(a), "l"(b)); return r;
}

// ---------------- warp-mma helpers ------------------------------------------
__device__ __forceinline__ uint32_t s2u(const void* p) {
    uint32_t a;
    asm("{ .reg .u64 t; cvta.to.shared.u64 t, %1; cvt.u32.u64 %0, t; }" : "=r"(a) : "l"(p));
    return a;
}
__device__ __forceinline__ void ldm4(uint32_t* r, uint32_t addr) {
    asm volatile("ldmatrix.sync.aligned.m8n8.x4.shared.b16 {%0,%1,%2,%3}, [%4];"
                 : "=r"(r[0]), "=r"(r[1]), "=r"(r[2]), "=r"(r[3]) : "r"(addr));
}
__device__ __forceinline__ void mma16816(float* d, const uint32_t* a, uint32_t b0, uint32_t b1) {
    asm volatile("mma.sync.aligned.m16n8k16.row.col.f32.bf16.bf16.f32 "
                 "{%0,%1,%2,%3}, {%4,%5,%6,%7}, {%8,%9}, {%0,%1,%2,%3};"
                 : "+f"(d[0]), "+f"(d[1]), "+f"(d[2]), "+f"(d[3])
                 : "r"(a[0]), "r"(a[1]), "r"(a[2]), "r"(a[3]), "r"(b0), "r"(b1));
}
#define STS128(a, v) \
    asm volatile("st.shared.v4.b32 [%0], {%1,%2,%3,%4};" :: "r"(a), "r"((v).x), "r"((v).y), "r"((v).z), "r"((v).w))
#define STS32(a, v) asm volatile("st.shared.b32 [%0], %1;" :: "r"(a), "r"(v))
#define CP_ASYNC16(d, s) asm volatile("cp.async.cg.shared.global [%0], [%1], 16;" :: "r"(d), "l"(s))
#define CP_COMMIT()      asm volatile("cp.async.commit_group;" ::: "memory")
#define CP_WAIT_ALL()    asm volatile("cp.async.wait_all;" ::: "memory")
#define CP_WAIT_1()      asm volatile("cp.async.wait_group 1;" ::: "memory")
#define CP_WAIT_0()      asm volatile("cp.async.wait_group 0;" ::: "memory")

// smem layout (bytes): bias[512 f32] | A hi [64x264 bf16] | A lo | W: 1 buffer x 2 tiles
#define SA_STRIDE 528
#define ALO_OFF   33792
#define W_STRIDE  144
#define W_TILE    18432
#define OFF_A     2048
#define OFF_W     (OFF_A + 2 * 33792)     // 69632
#define LSMEM     (OFF_W + 2 * W_TILE)    // 106496  -> 2 CTAs/SM

// ---------------------------------------------------------------------------
// Weight prep (coalesced): smem-tiled transpose + bf16 hi/lo split.
// 480 blocks x 256 threads. Block handles 32 kc x 128 n of one source matrix.
__global__ void prep_kernel(const float* __restrict__ fw, const float* __restrict__ gw,
                            const float* __restrict__ sw, const float* __restrict__ rw)
{
    __shared__ float s[32][129];
    const int bid = blockIdx.x, tid = threadIdx.x;
    const float* src;
    __nv_bfloat16 *dstHi, *dstLo;
    int kbase;
    if (bid < 320) {
        int l = bid >> 4, r = bid & 15;
        int gate = r >> 3, tap = (r >> 2) & 1, kb = r & 3;
        src = (gate ? gw : fw) + (((size_t)l * 2 + tap) * 128 + kb * 32) * 128;
        int c = tap * 2 + (kb >> 1);
        kbase = (kb & 1) * 32;
        dstHi = g_wfg + ((size_t)l * 16 + gate * 8 + c) * 8192;
        dstLo = g_wfg + ((size_t)l * 16 + gate * 8 + 4 + c) * 8192;
    } else {
        int b2 = bid - 320;
        int l = b2 >> 3, r = b2 & 7;
        int mat = r >> 2, kb = r & 3;
        src = (mat ? rw : sw) + ((size_t)l * 128 + kb * 32) * 128;
        int c = kb >> 1;
        kbase = (kb & 1) * 32;
        dstHi = g_wsr + ((size_t)l * 8 + mat * 4 + c) * 8192;
        dstLo = g_wsr + ((size_t)l * 8 + mat * 4 + 2 + c) * 8192;
    }
    #pragma unroll
    for (int i = 0; i < 16; i++) {
        int idx = i * 256 + tid;
        s[idx >> 7][idx & 127] = src[idx];
    }
    __syncthreads();
    #pragma unroll
    for (int j = 0; j < 16; j++) {
        int idx = j * 256 + tid;
        int n = idx >> 5, k = idx & 31;
        float v = s[k][n];
        __nv_bfloat16 hi = __float2bfloat16(v);
        __nv_bfloat16 lo = __float2bfloat16(v - __bfloat162float(hi));
        dstHi[(size_t)n * 64 + kbase + k] = hi;
        dstLo[(size_t)n * 64 + kbase + k] = lo;
    }
}

// stage one phase's weights (hi tile + lo tile) into the W buffer via cp.async
__device__ __forceinline__ void stage2(uint32_t dst, const __nv_bfloat16* __restrict__ hi,
                                       const __nv_bfloat16* __restrict__ lo, int tid)
{
    #pragma unroll
    for (int r = 0; r < 8; r++) {
        int i = r * 256 + tid;
        int t = i >> 10, u = i & 1023, n = u >> 3, ku = u & 7;
        const __nv_bfloat16* s = (t ? lo : hi) + (size_t)n * 64 + ku * 8;
        CP_ASYNC16(dst + t * W_TILE + n * W_STRIDE + ku * 16, s);
    }
}

// one phase of MMAs: acc += A(hi,lo) x W(hi,lo) over k-chunk cc
#define COMPUTE_PHASE(ACC, cc) do {                                            \
    _Pragma("unroll")                                                          \
    for (int ks = 0; ks < 4; ks++) {                                           \
        const int kA2 = ((cc) * 64 + ks * 16) * 2, kW2 = ks * 32;              \
        uint32_t ah[2][4], al[2][4], bh[2][4], bl[2][4];                       \
        ldm4(ah[0], aBase + kA2);                                              \
        ldm4(ah[1], aBase + 16 * SA_STRIDE + kA2);                             \
        ldm4(al[0], aBase + ALO_OFF + kA2);                                    \
        ldm4(al[1], aBase + ALO_OFF + 16 * SA_STRIDE + kA2);                   \
        ldm4(bh[0], bB + kW2);                                                 \
        ldm4(bh[1], bB + 16 * W_STRIDE + kW2);                                 \
        ldm4(bl[0], bB + W_TILE + kW2);                                        \
        ldm4(bl[1], bB + W_TILE + 16 * W_STRIDE + kW2);                        \
        _Pragma("unroll")                                                      \
        for (int mt = 0; mt < 2; mt++)                                         \
            _Pragma("unroll")                                                  \
            for (int nq = 0; nq < 4; nq++) {                                   \
                int nt = nq >> 1, pr = (nq & 1) * 2;                           \
                mma16816(ACC[mt][nq], ah[mt], bh[nt][pr], bh[nt][pr + 1]);     \
                mma16816(ACC[mt][nq], ah[mt], bl[nt][pr], bl[nt][pr + 1]);     \
                mma16816(ACC[mt][nq], al[mt], bh[nt][pr], bh[nt][pr + 1]);     \
            }                                                                  \
    }                                                                          \
} while (0)

// ---------------------------------------------------------------------------
// Tensor-core WaveNet layer (R12 structure: single W buffer, 2 CTAs/SM).
__global__ void __launch_bounds__(256, 2) tlayer_kernel(
    const float* __restrict__ res_in, float* __restrict__ res_out,
    float* __restrict__ out_acc,
    const __nv_bfloat16* __restrict__ wfg, const __nv_bfloat16* __restrict__ wsr,
    const float* __restrict__ fb, const float* __restrict__ gb,
    const float* __restrict__ sb, const float* __restrict__ rb,
    int d, int first)
{
    extern __shared__ char smem[];
    float* sbias = (float*)smem;
    const uint32_t sbase = s2u(smem);
    const uint32_t sA = sbase + OFF_A;
    const uint32_t sW = sbase + OFF_W;

    const int tid = threadIdx.x, wid = tid >> 5, lane = tid & 31;
    const int row0 = blockIdx.x * TM;
    const int batchStart = (row0 / T_LEN) * T_LEN;

    // prefetch phase-0 weights (f, chunk 0) while we stage A
    stage2(sW, wfg, wfg + (size_t)4 * 8192, tid);
    CP_COMMIT();

    for (int i = tid; i < 512; i += 256) {
        int grp = i >> 7, n = i & 127;
        const float* p = grp == 0 ? fb : grp == 1 ? gb : grp == 2 ? sb : rb;
        sbias[i] = p[n];
    }

    // ---- stage A = [prev(128) | cur(128)] as bf16 hi/lo, row-major [64][264]
    for (int idx = tid; idx < 2048; idx += 256) {
        int row = idx >> 5, ch = (idx & 31) * 8;
        int srow, c2;
        if (ch < 128) { srow = row0 + row - d; c2 = ch; }
        else          { srow = row0 + row;     c2 = ch - 128; }
        float v[8];
        if (srow >= batchStart) {
            const float4* sp = (const float4*)(res_in + (size_t)srow * RCH + c2);
            float4 a = sp[0], b2 = sp[1];
            v[0]=a.x; v[1]=a.y; v[2]=a.z; v[3]=a.w; v[4]=b2.x; v[5]=b2.y; v[6]=b2.z; v[7]=b2.w;
        } else {
            #pragma unroll
            for (int q = 0; q < 8; q++) v[q] = 0.f;
        }
        uint4 hp, lp;
        uint32_t* hw = (uint32_t*)&hp;
        uint32_t* lw = (uint32_t*)&lp;
        #pragma unroll
        for (int q = 0; q < 4; q++) {
            __nv_bfloat16 h0 = __float2bfloat16(v[2*q]),   h1 = __float2bfloat16(v[2*q+1]);
            __nv_bfloat16 l0 = __float2bfloat16(v[2*q]   - __bfloat162float(h0));
            __nv_bfloat16 l1 = __float2bfloat16(v[2*q+1] - __bfloat162float(h1));
            hw[q] = (uint32_t)__bfloat16_as_ushort(h0) | ((uint32_t)__bfloat16_as_ushort(h1) << 16);
            lw[q] = (uint32_t)__bfloat16_as_ushort(l0) | ((uint32_t)__bfloat16_as_ushort(l1) << 16);
        }
        uint32_t dst = sA + row * SA_STRIDE + ch * 2;
        STS128(dst, hp);
        STS128(dst + ALO_OFF, lp);
    }
    CP_WAIT_ALL();
    __syncthreads();

    // ldmatrix lane addressing
    const int mbase = (wid & 1) * 32;
    const int nbase = (wid >> 1) * 32;
    const int aRow = lane & 15, aCol = (lane >> 4) * 8;
    const int bm = lane >> 3;
    const int bRow = (lane & 7) + ((bm >> 1) * 8), bCol = (bm & 1) * 8;
    const uint32_t aBase = sA + (mbase + aRow) * SA_STRIDE + aCol * 2;
    const uint32_t bB = sW + (nbase + bRow) * W_STRIDE + bCol * 2;

    const int qrow = lane >> 2, qcol = (lane & 3) * 2;

    // ---- f/g: 8 phases (gate = p&1, chunk = p>>1); single W buffer
    {
        float accf[2][4][4], accg[2][4][4];
        #pragma unroll
        for (int mt = 0; mt < 2; mt++)
            #pragma unroll
            for (int nq = 0; nq < 4; nq++)
                #pragma unroll
                for (int q = 0; q < 4; q++) { accf[mt][nq][q] = 0.f; accg[mt][nq][q] = 0.f; }

        for (int p = 0; p < 8; p++) {
            int c = p >> 1;
            if (p & 1) COMPUTE_PHASE(accg, c);
            else       COMPUTE_PHASE(accf, c);
            __syncthreads();            // all warps done reading W
            if (p < 7) {
                int pn = p + 1, cn = pn >> 1, gate = pn & 1;
                stage2(sW, wfg + (size_t)(gate * 8 + cn) * 8192,
                           wfg + (size_t)(gate * 8 + 4 + cn) * 8192, tid);
            } else {
                stage2(sW, wsr, wsr + (size_t)2 * 8192, tid);   // sr phase 0
            }
            CP_COMMIT();
            CP_WAIT_ALL();
            __syncthreads();            // W ready (also: A reads done before epilogue)
        }

        // ---- gate epilogue: p = tanh(f+fb)*sigmoid(g+gb) -> hi/lo into A buffer
        #pragma unroll
        for (int mt = 0; mt < 2; mt++)
            #pragma unroll
            for (int nq = 0; nq < 4; nq++)
                #pragma unroll
                for (int rp = 0; rp < 2; rp++) {
                    int row = mbase + mt * 16 + qrow + rp * 8;
                    int col = nbase + nq * 8 + qcol;
                    float f0 = tanhf(accf[mt][nq][rp * 2]     + sbias[col]);
                    float f1 = tanhf(accf[mt][nq][rp * 2 + 1] + sbias[col + 1]);
                    float g0 = 1.f / (1.f + __expf(-(accg[mt][nq][rp * 2]     + sbias[128 + col])));
                    float g1 = 1.f / (1.f + __expf(-(accg[mt][nq][rp * 2 + 1] + sbias[128 + col + 1])));
                    float p0 = f0 * g0, p1 = f1 * g1;
                    __nv_bfloat16 h0 = __float2bfloat16(p0), h1 = __float2bfloat16(p1);
                    __nv_bfloat16 l0 = __float2bfloat16(p0 - __bfloat162float(h0));
                    __nv_bfloat16 l1 = __float2bfloat16(p1 - __bfloat162float(h1));
                    uint32_t hv = (uint32_t)__bfloat16_as_ushort(h0) | ((uint32_t)__bfloat16_as_ushort(h1) << 16);
                    uint32_t lv = (uint32_t)__bfloat16_as_ushort(l0) | ((uint32_t)__bfloat16_as_ushort(l1) << 16);
                    uint32_t dst = sA + row * SA_STRIDE + col * 2;
                    STS32(dst, hv);
                    STS32(dst + ALO_OFF, lv);
                }
    }
    __syncthreads();

    // ---- skip/res: 4 phases (skip c0, res c0, skip c1, res c1)
    float accs[2][4][4], accr[2][4][4];
    #pragma unroll
    for (int mt = 0; mt < 2; mt++)
        #pragma unroll
        for (int nq = 0; nq < 4; nq++)
            #pragma unroll
            for (int q = 0; q < 4; q++) { accs[mt][nq][q] = 0.f; accr[mt][nq][q] = 0.f; }

    for (int q = 0; q < 4; q++) {
        int c = q >> 1;
        if (q & 1) COMPUTE_PHASE(accr, c);
        else       COMPUTE_PHASE(accs, c);
        if (q < 3) {
            __syncthreads();
            int qn = q + 1, mat = qn & 1, cn = qn >> 1;
            stage2(sW, wsr + (size_t)(mat * 4 + cn) * 8192,
                       wsr + (size_t)(mat * 4 + 2 + cn) * 8192, tid);
            CP_COMMIT();
            CP_WAIT_ALL();
            __syncthreads();
        }
    }

    // ---- final epilogue
    #pragma unroll
    for (int mt = 0; mt < 2; mt++)
        #pragma unroll
        for (int nq = 0; nq < 4; nq++)
            #pragma unroll
            for (int rp = 0; rp < 2; rp++) {
                int row = mbase + mt * 16 + qrow + rp * 8;
                int col = nbase + nq * 8 + qcol;
                int grow = row0 + row;
                float s0 = accs[mt][nq][rp * 2]     + sbias[256 + col];
                float s1 = accs[mt][nq][rp * 2 + 1] + sbias[256 + col + 1];
                float* oa = out_acc + (size_t)grow * RCH + col;
                if (!first) {
                    float2 oo = *(const float2*)oa;
                    s0 += oo.x; s1 += oo.y;
                }
                *(float2*)oa = make_float2(s0, s1);
                float2 rv = *(const float2*)(res_in + (size_t)grow * RCH + col);
                float r0 = rv.x + accr[mt][nq][rp * 2]     + sbias[384 + col];
                float r1 = rv.y + accr[mt][nq][rp * 2 + 1] + sbias[384 + col + 1];
                *(float2*)(res_out + (size_t)grow * RCH + col) = make_float2(r0, r1);
            }
}

// ---------------------------------------------------------------------------
// Initial causal conv: K=32, 64 -> 128, dilation 1.  128 thr, 8x8 tile.
// cp.async double-buffered tap weight staging.
#define INIT_XT_F   (95 * 64)             // 6080 floats
#define INIT_WB_OFF (INIT_XT_F * 4)       // byte offset of weight buffers
#define INIT_SMEM   ((INIT_XT_F + 2 * 8192) * 4)   // 89856 B -> 2 blocks/SM

__global__ void __launch_bounds__(128, 2) init_kernel(
    const float* __restrict__ X, const float* __restrict__ W,
    const float* __restrict__ B, float* __restrict__ res_out)
{
    extern __shared__ float sm[];
    float* xt = sm;
    float* wb = sm + INIT_XT_F;           // two 8192-float buffers
    const uint32_t wb32 = s2u(sm) + INIT_WB_OFF;
    const int tid  = threadIdx.x;
    const int row0 = blockIdx.x * TM;
    const int batchStart = (row0 / T_LEN) * T_LEN;

    // prefetch tap 0 weights
    #pragma unroll
    for (int r = 0; r < 16; r++) {
        int i = r * 128 + tid;
        CP_ASYNC16(wb32 + i * 16, W + (size_t)i * 4);
    }
    CP_COMMIT();

    for (int i = tid; i < 95 * 16; i += NT) {
        int r = i >> 4, c4 = i & 15;
        int src = row0 - 31 + r;
        float4 v = make_float4(0.f, 0.f, 0.f, 0.f);
        if (src >= batchStart) v = ((const float4*)(X + (size_t)src * 64))[c4];
        ((float4*)(xt + r * 64))[c4] = v;
    }

    const int ty = tid >> 4, tx = tid & 15;
    const int r0 = ty * 8, c0 = tx * 8;

    ull acc[8][4];
    #pragma unroll
    for (int j = 0; j < 4; j++) {
        ull b = pk2(B[c0 + 2*j], B[c0 + 2*j + 1]);
        #pragma unroll
        for (int rr = 0; rr < 8; rr++) acc[rr][j] = b;
    }

    for (int j = 0; j < 32; j++) {
        if (j < 31) {
            const float* ws = W + (size_t)(j + 1) * 8192;
            uint32_t dst = wb32 + (uint32_t)(((j + 1) & 1) ? 32768 : 0);
            #pragma unroll
            for (int r = 0; r < 16; r++) {
                int i = r * 128 + tid;
                CP_ASYNC16(dst + i * 16, ws + (size_t)i * 4);
            }
            CP_COMMIT();
            CP_WAIT_1();
        } else {
            CP_WAIT_0();
        }
        __syncthreads();
        const float* wcur = wb + (j & 1) * 8192;
        #pragma unroll 2
        for (int kk = 0; kk < 64; kk += 2) {
            float2 ap[8];
            #pragma unroll
            for (int rr = 0; rr < 8; rr++)
                ap[rr] = *(const float2*)(xt + (r0 + rr + j) * 64 + kk);
            #pragma unroll
            for (int q = 0; q < 2; q++) {
                const float* wp = wcur + (kk + q) * 128 + c0;
                ulonglong2 wa = *(const ulonglong2*)wp;
                ulonglong2 wc = *(const ulonglong2*)(wp + 4);
                #pragma unroll
                for (int rr = 0; rr < 8; rr++) {
                    float a = q ? ap[rr].y : ap[rr].x;
                    ull ad = pk2(a, a);
                    fma2(acc[rr][0], ad, wa.x);
                    fma2(acc[rr][1], ad, wa.y);
                    fma2(acc[rr][2], ad, wc.x);
                    fma2(acc[rr][3], ad, wc.y);
                }
            }
        }
        __syncthreads();
    }
    #pragma unroll
    for (int rr = 0; rr < 8; rr++) {
        float o[8];
        #pragma unroll
        for (int j = 0; j < 4; j++) upk2(acc[rr][j], o[2*j], o[2*j+1]);
        float* dst = res_out + (size_t)(row0 + r0 + rr) * RCH + c0;
        ((float4*)dst)[0] = make_float4(o[0], o[1], o[2], o[3]);
        ((float4*)dst)[1] = make_float4(o[4], o[5], o[6], o[7]);
    }
}

// ---------------------------------------------------------------------------
// Post chain: 1024 threads/block (32 warps/SM) to hide the serial shfl chain.
__global__ void __launch_bounds__(1024) post_kernel(
    const float* __restrict__ out_acc,
    const float* __restrict__ s0w, const float* __restrict__ s0b,
    const float* __restrict__ srw, const float* __restrict__ srb,
    const float* __restrict__ fnw, const float* __restrict__ fnb,
    float* __restrict__ y)
{
    extern __shared__ float sm[];
    float* w0 = sm;
    float* wr = w0 + 4096;
    float* wf = wr + 31744;
    float* b0 = wf + 8192;
    float* br = b0 + 32;
    float* bf = br + 992;

    const int tid = threadIdx.x;
    for (int i = tid; i < 4096;  i += blockDim.x) w0[i] = s0w[i];
    for (int i = tid; i < 31744; i += blockDim.x) wr[i] = srw[i];
    for (int i = tid; i < 8192;  i += blockDim.x) wf[i] = fnw[i];
    for (int i = tid; i < 32;    i += blockDim.x) b0[i] = s0b[i];
    for (int i = tid; i < 992;   i += blockDim.x) br[i] = srb[i];
    for (int i = tid; i < 256;   i += blockDim.x) bf[i] = fnb[i];
    __syncthreads();

    const int warp = tid >> 5, lane = tid & 31;
    const int nwarp = blockDim.x >> 5;

    for (int pr = blockIdx.x * nwarp + warp; pr < BT / 2; pr += gridDim.x * nwarp) {
        const int rowA = pr * 2, rowB = pr * 2 + 1;
        float4 xa = ((const float4*)(out_acc + (size_t)rowA * RCH))[lane];
        float4 xb = ((const float4*)(out_acc + (size_t)rowB * RCH))[lane];
        xa.x = fmaxf(xa.x, 0.f); xa.y = fmaxf(xa.y, 0.f); xa.z = fmaxf(xa.z, 0.f); xa.w = fmaxf(xa.w, 0.f);
        xb.x = fmaxf(xb.x, 0.f); xb.y = fmaxf(xb.y, 0.f); xb.z = fmaxf(xb.z, 0.f); xb.w = fmaxf(xb.w, 0.f);
        ull xp0 = pk2(xa.x, xb.x), xp1 = pk2(xa.y, xb.y);
        ull xp2 = pk2(xa.z, xb.z), xp3 = pk2(xa.w, xb.w);

        float bb = b0[lane];
        ull h = pk2(bb, bb);
        #pragma unroll
        for (int s = 0; s < 32; s++) {
            ull v0 = __shfl_sync(0xffffffffu, xp0, s);
            ull v1 = __shfl_sync(0xffffffffu, xp1, s);
            ull v2 = __shfl_sync(0xffffffffu, xp2, s);
            ull v3 = __shfl_sync(0xffffffffu, xp3, s);
            float wv0 = w0[(s*4+0)*32 + lane];
            float wv1 = w0[(s*4+1)*32 + lane];
            float wv2 = w0[(s*4+2)*32 + lane];
            float wv3 = w0[(s*4+3)*32 + lane];
            fma2(h, v0, pk2(wv0, wv0));
            fma2(h, v1, pk2(wv1, wv1));
            fma2(h, v2, pk2(wv2, wv2));
            fma2(h, v3, pk2(wv3, wv3));
        }
        for (int li = 0; li < 31; li++) {
            float hl, hh; upk2(h, hl, hh);
            ull rv = pk2(fmaxf(hl, 0.f), fmaxf(hh, 0.f));
            const float* wp = wr + li * 1024;
            float bl = br[li*32 + lane];
            ull ha = pk2(bl, bl);
            ull hb = pk2(0.f, 0.f);
            #pragma unroll
            for (int s = 0; s < 32; s += 2) {
                ull ra  = __shfl_sync(0xffffffffu, rv, s);
                ull rb2 = __shfl_sync(0xffffffffu, rv, s + 1);
                float wA = wp[(s    )*32 + lane];
                float wB = wp[(s + 1)*32 + lane];
                fma2(ha, ra,  pk2(wA, wA));
                fma2(hb, rb2, pk2(wB, wB));
            }
            h = add2(ha, hb);
        }
        float hl, hh; upk2(h, hl, hh);
        ull rv = pk2(fmaxf(hl, 0.f), fmaxf(hh, 0.f));
        ull accP[8];
        #pragma unroll
        for (int u = 0; u < 8; u++) {
            float b = bf[lane*8 + u];
            accP[u] = pk2(b, b);
        }
        #pragma unroll
        for (int s = 0; s < 32; s++) {
            ull rs = __shfl_sync(0xffffffffu, rv, s);
            const float* wp = wf + s*256 + lane*8;
            float4 wq0 = *(const float4*)wp;
            float4 wq1 = *(const float4*)(wp + 4);
            fma2(accP[0], rs, pk2(wq0.x, wq0.x));
            fma2(accP[1], rs, pk2(wq0.y, wq0.y));
            fma2(accP[2], rs, pk2(wq0.z, wq0.z));
            fma2(accP[3], rs, pk2(wq0.w, wq0.w));
            fma2(accP[4], rs, pk2(wq1.x, wq1.x));
            fma2(accP[5], rs, pk2(wq1.y, wq1.y));
            fma2(accP[6], rs, pk2(wq1.z, wq1.z));
            fma2(accP[7], rs, pk2(wq1.w, wq1.w));
        }
        float oa[8], ob[8];
        #pragma unroll
        for (int u = 0; u < 8; u++) upk2(accP[u], oa[u], ob[u]);
        float4* ya = (float4*)(y + (size_t)rowA * 256 + lane * 8);
        ya[0] = make_float4(oa[0], oa[1], oa[2], oa[3]);
        ya[1] = make_float4(oa[4], oa[5], oa[6], oa[7]);
        float4* yb = (float4*)(y + (size_t)rowB * 256 + lane * 8);
        yb[0] = make_float4(ob[0], ob[1], ob[2], ob[3]);
        yb[1] = make_float4(ob[4], ob[5], ob[6], ob[7]);
    }
}

// ---------------------------------------------------------------------------
extern "C" void kernel_launch(void* const* d_in, const int* in_sizes, int n_in,
                              void* d_out, int out_size)
{
    const float* X       = (const float*)d_in[0];
    const float* init_w  = (const float*)d_in[1];
    const float* init_b  = (const float*)d_in[2];
    const float* f_w     = (const float*)d_in[3];
    const float* f_b     = (const float*)d_in[4];
    const float* g_w     = (const float*)d_in[5];
    const float* g_b     = (const float*)d_in[6];
    const float* skip_w  = (const float*)d_in[7];
    const float* skip_b  = (const float*)d_in[8];
    const float* res_w   = (const float*)d_in[9];
    const float* res_b   = (const float*)d_in[10];
    const float* skip0_w = (const float*)d_in[11];
    const float* skip0_b = (const float*)d_in[12];
    const float* skipr_w = (const float*)d_in[13];
    const float* skipr_b = (const float*)d_in[14];
    const float* final_w = (const float*)d_in[15];
    const float* final_b = (const float*)d_in[16];
    float* y = (float*)d_out;

    float *resA, *resB, *outacc;
    __nv_bfloat16 *wfg, *wsr;
    cudaGetSymbolAddress((void**)&resA,   g_resA);
    cudaGetSymbolAddress((void**)&resB,   g_resB);
    cudaGetSymbolAddress((void**)&outacc, g_outacc);
    cudaGetSymbolAddress((void**)&wfg,    g_wfg);
    cudaGetSymbolAddress((void**)&wsr,    g_wsr);

    const int POST_SMEM = (4096 + 31744 + 8192 + 32 + 992 + 256) * 4;
    cudaFuncSetAttribute(init_kernel,   cudaFuncAttributeMaxDynamicSharedMemorySize, INIT_SMEM);
    cudaFuncSetAttribute(tlayer_kernel, cudaFuncAttributeMaxDynamicSharedMemorySize, LSMEM);
    cudaFuncSetAttribute(post_kernel,   cudaFuncAttributeMaxDynamicSharedMemorySize, POST_SMEM);

    prep_kernel<<<480, 256>>>(f_w, g_w, skip_w, res_w);
    init_kernel<<<BT / TM, NT, INIT_SMEM>>>(X, init_w, init_b, resA);

    static const int DIL[20] = {1,2,4,8,16,32,64,128,256,512,
                                1,2,4,8,16,32,64,128,256,512};
    for (int i = 0; i < 20; i++) {
        const float* rin  = (i & 1) ? resB : resA;
        float*       rout = (i & 1) ? resA : resB;
        tlayer_kernel<<<BT / TM, 256, LSMEM>>>(
            rin, rout, outacc,
            wfg + (size_t)i * 16 * 8192, wsr + (size_t)i * 8 * 8192,
            f_b + i * RCH, g_b + i * RCH, skip_b + i * RCH, res_b + i * RCH,
            DIL[i], (i == 0) ? 1 : 0);
    }

    post_kernel<<<296, 1024, POST_SMEM>>>(outacc, skip0_w, skip0_b,
                                          skipr_w, skipr_b, final_w, final_b, y);
}

// round 17
// speedup vs baseline: 1.1624x; 1.1143x over previous
#include <cuda_runtime.h>
#include <cuda_bf16.h>
#include <math.h>
#include <stdint.h>

typedef unsigned long long ull;

#define BT    65536
#define T_LEN 16384
#define RCH   128
#define TM    64

// ---------------- scratch ---------------------------------------------------
__device__ float g_resA[BT * RCH];
__device__ float g_resB[BT * RCH];
__device__ float g_outacc[BT * RCH];
__device__ __nv_bfloat16 g_wfg[20 * 16 * 8192];
__device__ __nv_bfloat16 g_wsr[20 * 8 * 8192];
__device__ __nv_bfloat16 g_wi[64 * 8192];     // init conv: 32 taps x (hi,lo) [128n x 64k]

// ---------------- packed f32x2 helpers --------------------------------------
__device__ __forceinline__ ull pk2(float lo, float hi) {
    ull r; asm("mov.b64 %0, {%1, %2};" : "=l"(r) : "f"(lo), "f"(hi)); return r;
}
__device__ __forceinline__ void upk2(ull v, float& lo, float& hi) {
    asm("mov.b64 {%0, %1}, %2;" : "=f"(lo), "=f"(hi) : "l"(v));
}
__device__ __forceinline__ void fma2(ull& d, ull a, ull b) {
    asm("fma.rn.f32x2 %0, %1, %2, %0;" : "+l"(d) : "l"(a), "l"(b));
}
__device__ __forceinline__ ull add2(ull a, ull b) {
    ull r; asm("add.rn.f32x2 %0, %1, %2;" : "=l"(r) : "l"(a), "l"(b)); return r;
}

// ---------------- warp-mma helpers ------------------------------------------
__device__ __forceinline__ uint32_t s2u(const void* p) {
    uint32_t a;
    asm("{ .reg .u64 t; cvta.to.shared.u64 t, %1; cvt.u32.u64 %0, t; }" : "=r"(a) : "l"(p));
    return a;
}
__device__ __forceinline__ void ldm4(uint32_t* r, uint32_t addr) {
    asm volatile("ldmatrix.sync.aligned.m8n8.x4.shared.b16 {%0,%1,%2,%3}, [%4];"
                 : "=r"(r[0]), "=r"(r[1]), "=r"(r[2]), "=r"(r[3]) : "r"(addr));
}
__device__ __forceinline__ void mma16816(float* d, const uint32_t* a, uint32_t b0, uint32_t b1) {
    asm volatile("mma.sync.aligned.m16n8k16.row.col.f32.bf16.bf16.f32 "
                 "{%0,%1,%2,%3}, {%4,%5,%6,%7}, {%8,%9}, {%0,%1,%2,%3};"
                 : "+f"(d[0]), "+f"(d[1]), "+f"(d[2]), "+f"(d[3])
                 : "r"(a[0]), "r"(a[1]), "r"(a[2]), "r"(a[3]), "r"(b0), "r"(b1));
}
#define STS128(a, v) \
    asm volatile("st.shared.v4.b32 [%0], {%1,%2,%3,%4};" :: "r"(a), "r"((v).x), "r"((v).y), "r"((v).z), "r"((v).w))
#define STS32(a, v) asm volatile("st.shared.b32 [%0], %1;" :: "r"(a), "r"(v))
#define CP_ASYNC16(d, s) asm volatile("cp.async.cg.shared.global [%0], [%1], 16;" :: "r"(d), "l"(s))
#define CP_COMMIT()      asm volatile("cp.async.commit_group;" ::: "memory")
#define CP_WAIT_ALL()    asm volatile("cp.async.wait_all;" ::: "memory")
#define CP_WAIT_1()      asm volatile("cp.async.wait_group 1;" ::: "memory")
#define CP_WAIT_0()      asm volatile("cp.async.wait_group 0;" ::: "memory")

// layer smem layout (bytes)
#define SA_STRIDE 528
#define ALO_OFF   33792
#define W_STRIDE  144
#define W_TILE    18432
#define OFF_A     2048
#define OFF_W     (OFF_A + 2 * 33792)     // 69632
#define LSMEM     (OFF_W + 2 * W_TILE)    // 106496  -> 2 CTAs/SM

// init smem layout (bytes)
#define OFF_P     512
#define PLO_OFF   (96 * 144)              // 13824
#define OFF_IW    (OFF_P + 2 * PLO_OFF)   // 28160
#define IW_BUF    (2 * W_TILE)            // 36864 (hi+lo, 144-B stride)
#define ISMEM     (OFF_IW + 2 * IW_BUF)   // 101888 -> 2 CTAs/SM

// ---------------------------------------------------------------------------
// Weight prep (coalesced transpose + bf16 hi/lo split). 544 blocks x 256 thr.
__global__ void prep_kernel(const float* __restrict__ fw, const float* __restrict__ gw,
                            const float* __restrict__ sw, const float* __restrict__ rw,
                            const float* __restrict__ iw)
{
    __shared__ float s[32][129];
    const int bid = blockIdx.x, tid = threadIdx.x;
    const float* src;
    __nv_bfloat16 *dstHi, *dstLo;
    int kbase;
    if (bid < 320) {
        int l = bid >> 4, r = bid & 15;
        int gate = r >> 3, tap = (r >> 2) & 1, kb = r & 3;
        src = (gate ? gw : fw) + (((size_t)l * 2 + tap) * 128 + kb * 32) * 128;
        int c = tap * 2 + (kb >> 1);
        kbase = (kb & 1) * 32;
        dstHi = g_wfg + ((size_t)l * 16 + gate * 8 + c) * 8192;
        dstLo = g_wfg + ((size_t)l * 16 + gate * 8 + 4 + c) * 8192;
    } else if (bid < 480) {
        int b2 = bid - 320;
        int l = b2 >> 3, r = b2 & 7;
        int mat = r >> 2, kb = r & 3;
        src = (mat ? rw : sw) + ((size_t)l * 128 + kb * 32) * 128;
        int c = kb >> 1;
        kbase = (kb & 1) * 32;
        dstHi = g_wsr + ((size_t)l * 8 + mat * 4 + c) * 8192;
        dstLo = g_wsr + ((size_t)l * 8 + mat * 4 + 2 + c) * 8192;
    } else {
        int b3 = bid - 480;
        int tap = b3 >> 1, kb = b3 & 1;
        src = iw + ((size_t)tap * 64 + kb * 32) * 128;
        kbase = kb * 32;
        dstHi = g_wi + (size_t)tap * 8192;
        dstLo = g_wi + (size_t)(32 + tap) * 8192;
    }
    #pragma unroll
    for (int i = 0; i < 16; i++) {
        int idx = i * 256 + tid;
        s[idx >> 7][idx & 127] = src[idx];
    }
    __syncthreads();
    #pragma unroll
    for (int j = 0; j < 16; j++) {
        int idx = j * 256 + tid;
        int n = idx >> 5, k = idx & 31;
        float v = s[k][n];
        __nv_bfloat16 hi = __float2bfloat16(v);
        __nv_bfloat16 lo = __float2bfloat16(v - __bfloat162float(hi));
        dstHi[(size_t)n * 64 + kbase + k] = hi;
        dstLo[(size_t)n * 64 + kbase + k] = lo;
    }
}

// stage one phase's weights (hi tile + lo tile) into a W buffer via cp.async
__device__ __forceinline__ void stage2(uint32_t dst, const __nv_bfloat16* __restrict__ hi,
                                       const __nv_bfloat16* __restrict__ lo, int tid)
{
    #pragma unroll
    for (int r = 0; r < 8; r++) {
        int i = r * 256 + tid;
        int t = i >> 10, u = i & 1023, n = u >> 3, ku = u & 7;
        const __nv_bfloat16* s = (t ? lo : hi) + (size_t)n * 64 + ku * 8;
        CP_ASYNC16(dst + t * W_TILE + n * W_STRIDE + ku * 16, s);
    }
}

// one phase of MMAs: acc += A(hi,lo) x W(hi,lo) over k-chunk cc  (layer kernel)
#define COMPUTE_PHASE(ACC, cc) do {                                            \
    _Pragma("unroll")                                                          \
    for (int ks = 0; ks < 4; ks++) {                                           \
        const int kA2 = ((cc) * 64 + ks * 16) * 2, kW2 = ks * 32;              \
        uint32_t ah[2][4], al[2][4], bh[2][4], bl[2][4];                       \
        ldm4(ah[0], aBase + kA2);                                              \
        ldm4(ah[1], aBase + 16 * SA_STRIDE + kA2);                             \
        ldm4(al[0], aBase + ALO_OFF + kA2);                                    \
        ldm4(al[1], aBase + ALO_OFF + 16 * SA_STRIDE + kA2);                   \
        ldm4(bh[0], bB + kW2);                                                 \
        ldm4(bh[1], bB + 16 * W_STRIDE + kW2);                                 \
        ldm4(bl[0], bB + W_TILE + kW2);                                        \
        ldm4(bl[1], bB + W_TILE + 16 * W_STRIDE + kW2);                        \
        _Pragma("unroll")                                                      \
        for (int mt = 0; mt < 2; mt++)                                         \
            _Pragma("unroll")                                                  \
            for (int nq = 0; nq < 4; nq++) {                                   \
                int nt = nq >> 1, pr = (nq & 1) * 2;                           \
                mma16816(ACC[mt][nq], ah[mt], bh[nt][pr], bh[nt][pr + 1]);     \
                mma16816(ACC[mt][nq], ah[mt], bl[nt][pr], bl[nt][pr + 1]);     \
                mma16816(ACC[mt][nq], al[mt], bh[nt][pr], bh[nt][pr + 1]);     \
            }                                                                  \
    }                                                                          \
} while (0)

// init phase: A rows shift with tap; panel stride 144 B
#define COMPUTE_INIT(ACC, aB, wb) do {                                         \
    _Pragma("unroll")                                                          \
    for (int ks = 0; ks < 4; ks++) {                                           \
        const int kA2 = ks * 32, kW2 = ks * 32;                                \
        uint32_t ah[2][4], al[2][4], bh[2][4], bl[2][4];                       \
        ldm4(ah[0], (aB) + kA2);                                               \
        ldm4(ah[1], (aB) + 16 * 144 + kA2);                                    \
        ldm4(al[0], (aB) + PLO_OFF + kA2);                                     \
        ldm4(al[1], (aB) + PLO_OFF + 16 * 144 + kA2);                          \
        ldm4(bh[0], (wb) + kW2);                                               \
        ldm4(bh[1], (wb) + 16 * W_STRIDE + kW2);                               \
        ldm4(bl[0], (wb) + W_TILE + kW2);                                      \
        ldm4(bl[1], (wb) + W_TILE + 16 * W_STRIDE + kW2);                      \
        _Pragma("unroll")                                                      \
        for (int mt = 0; mt < 2; mt++)                                         \
            _Pragma("unroll")                                                  \
            for (int nq = 0; nq < 4; nq++) {                                   \
                int nt = nq >> 1, pr = (nq & 1) * 2;                           \
                mma16816(ACC[mt][nq], ah[mt], bh[nt][pr], bh[nt][pr + 1]);     \
                mma16816(ACC[mt][nq], ah[mt], bl[nt][pr], bl[nt][pr + 1]);     \
                mma16816(ACC[mt][nq], al[mt], bh[nt][pr], bh[nt][pr + 1]);     \
            }                                                                  \
    }                                                                          \
} while (0)

// ---------------------------------------------------------------------------
// Tensor-core WaveNet layer (R12 structure: single W buffer, 2 CTAs/SM).
__global__ void __launch_bounds__(256, 2) tlayer_kernel(
    const float* __restrict__ res_in, float* __restrict__ res_out,
    float* __restrict__ out_acc,
    const __nv_bfloat16* __restrict__ wfg, const __nv_bfloat16* __restrict__ wsr,
    const float* __restrict__ fb, const float* __restrict__ gb,
    const float* __restrict__ sb, const float* __restrict__ rb,
    int d, int first)
{
    extern __shared__ char smem[];
    float* sbias = (float*)smem;
    const uint32_t sbase = s2u(smem);
    const uint32_t sA = sbase + OFF_A;
    const uint32_t sW = sbase + OFF_W;

    const int tid = threadIdx.x, wid = tid >> 5, lane = tid & 31;
    const int row0 = blockIdx.x * TM;
    const int batchStart = (row0 / T_LEN) * T_LEN;

    stage2(sW, wfg, wfg + (size_t)4 * 8192, tid);
    CP_COMMIT();

    for (int i = tid; i < 512; i += 256) {
        int grp = i >> 7, n = i & 127;
        const float* p = grp == 0 ? fb : grp == 1 ? gb : grp == 2 ? sb : rb;
        sbias[i] = p[n];
    }

    // ---- stage A = [prev(128) | cur(128)] as bf16 hi/lo, row-major [64][264]
    for (int idx = tid; idx < 2048; idx += 256) {
        int row = idx >> 5, ch = (idx & 31) * 8;
        int srow, c2;
        if (ch < 128) { srow = row0 + row - d; c2 = ch; }
        else          { srow = row0 + row;     c2 = ch - 128; }
        float v[8];
        if (srow >= batchStart) {
            const float4* sp = (const float4*)(res_in + (size_t)srow * RCH + c2);
            float4 a = sp[0], b2 = sp[1];
            v[0]=a.x; v[1]=a.y; v[2]=a.z; v[3]=a.w; v[4]=b2.x; v[5]=b2.y; v[6]=b2.z; v[7]=b2.w;
        } else {
            #pragma unroll
            for (int q = 0; q < 8; q++) v[q] = 0.f;
        }
        uint4 hp, lp;
        uint32_t* hw = (uint32_t*)&hp;
        uint32_t* lw = (uint32_t*)&lp;
        #pragma unroll
        for (int q = 0; q < 4; q++) {
            __nv_bfloat16 h0 = __float2bfloat16(v[2*q]),   h1 = __float2bfloat16(v[2*q+1]);
            __nv_bfloat16 l0 = __float2bfloat16(v[2*q]   - __bfloat162float(h0));
            __nv_bfloat16 l1 = __float2bfloat16(v[2*q+1] - __bfloat162float(h1));
            hw[q] = (uint32_t)__bfloat16_as_ushort(h0) | ((uint32_t)__bfloat16_as_ushort(h1) << 16);
            lw[q] = (uint32_t)__bfloat16_as_ushort(l0) | ((uint32_t)__bfloat16_as_ushort(l1) << 16);
        }
        uint32_t dst = sA + row * SA_STRIDE + ch * 2;
        STS128(dst, hp);
        STS128(dst + ALO_OFF, lp);
    }
    CP_WAIT_ALL();
    __syncthreads();

    const int mbase = (wid & 1) * 32;
    const int nbase = (wid >> 1) * 32;
    const int aRow = lane & 15, aCol = (lane >> 4) * 8;
    const int bm = lane >> 3;
    const int bRow = (lane & 7) + ((bm >> 1) * 8), bCol = (bm & 1) * 8;
    const uint32_t aBase = sA + (mbase + aRow) * SA_STRIDE + aCol * 2;
    const uint32_t bB = sW + (nbase + bRow) * W_STRIDE + bCol * 2;

    const int qrow = lane >> 2, qcol = (lane & 3) * 2;

    // ---- f/g: 8 phases
    {
        float accf[2][4][4], accg[2][4][4];
        #pragma unroll
        for (int mt = 0; mt < 2; mt++)
            #pragma unroll
            for (int nq = 0; nq < 4; nq++)
                #pragma unroll
                for (int q = 0; q < 4; q++) { accf[mt][nq][q] = 0.f; accg[mt][nq][q] = 0.f; }

        for (int p = 0; p < 8; p++) {
            int c = p >> 1;
            if (p & 1) COMPUTE_PHASE(accg, c);
            else       COMPUTE_PHASE(accf, c);
            __syncthreads();
            if (p < 7) {
                int pn = p + 1, cn = pn >> 1, gate = pn & 1;
                stage2(sW, wfg + (size_t)(gate * 8 + cn) * 8192,
                           wfg + (size_t)(gate * 8 + 4 + cn) * 8192, tid);
            } else {
                stage2(sW, wsr, wsr + (size_t)2 * 8192, tid);
            }
            CP_COMMIT();
            CP_WAIT_ALL();
            __syncthreads();
        }

        // gate epilogue
        #pragma unroll
        for (int mt = 0; mt < 2; mt++)
            #pragma unroll
            for (int nq = 0; nq < 4; nq++)
                #pragma unroll
                for (int rp = 0; rp < 2; rp++) {
                    int row = mbase + mt * 16 + qrow + rp * 8;
                    int col = nbase + nq * 8 + qcol;
                    float f0 = tanhf(accf[mt][nq][rp * 2]     + sbias[col]);
                    float f1 = tanhf(accf[mt][nq][rp * 2 + 1] + sbias[col + 1]);
                    float g0 = 1.f / (1.f + __expf(-(accg[mt][nq][rp * 2]     + sbias[128 + col])));
                    float g1 = 1.f / (1.f + __expf(-(accg[mt][nq][rp * 2 + 1] + sbias[128 + col + 1])));
                    float p0 = f0 * g0, p1 = f1 * g1;
                    __nv_bfloat16 h0 = __float2bfloat16(p0), h1 = __float2bfloat16(p1);
                    __nv_bfloat16 l0 = __float2bfloat16(p0 - __bfloat162float(h0));
                    __nv_bfloat16 l1 = __float2bfloat16(p1 - __bfloat162float(h1));
                    uint32_t hv = (uint32_t)__bfloat16_as_ushort(h0) | ((uint32_t)__bfloat16_as_ushort(h1) << 16);
                    uint32_t lv = (uint32_t)__bfloat16_as_ushort(l0) | ((uint32_t)__bfloat16_as_ushort(l1) << 16);
                    uint32_t dst = sA + row * SA_STRIDE + col * 2;
                    STS32(dst, hv);
                    STS32(dst + ALO_OFF, lv);
                }
    }
    __syncthreads();

    // ---- skip/res: 4 phases
    float accs[2][4][4], accr[2][4][4];
    #pragma unroll
    for (int mt = 0; mt < 2; mt++)
        #pragma unroll
        for (int nq = 0; nq < 4; nq++)
            #pragma unroll
            for (int q = 0; q < 4; q++) { accs[mt][nq][q] = 0.f; accr[mt][nq][q] = 0.f; }

    for (int q = 0; q < 4; q++) {
        int c = q >> 1;
        if (q & 1) COMPUTE_PHASE(accr, c);
        else       COMPUTE_PHASE(accs, c);
        if (q < 3) {
            __syncthreads();
            int qn = q + 1, mat = qn & 1, cn = qn >> 1;
            stage2(sW, wsr + (size_t)(mat * 4 + cn) * 8192,
                       wsr + (size_t)(mat * 4 + 2 + cn) * 8192, tid);
            CP_COMMIT();
            CP_WAIT_ALL();
            __syncthreads();
        }
    }

    // ---- final epilogue
    #pragma unroll
    for (int mt = 0; mt < 2; mt++)
        #pragma unroll
        for (int nq = 0; nq < 4; nq++)
            #pragma unroll
            for (int rp = 0; rp < 2; rp++) {
                int row = mbase + mt * 16 + qrow + rp * 8;
                int col = nbase + nq * 8 + qcol;
                int grow = row0 + row;
                float s0 = accs[mt][nq][rp * 2]     + sbias[256 + col];
                float s1 = accs[mt][nq][rp * 2 + 1] + sbias[256 + col + 1];
                float* oa = out_acc + (size_t)grow * RCH + col;
                if (!first) {
                    float2 oo = *(const float2*)oa;
                    s0 += oo.x; s1 += oo.y;
                }
                *(float2*)oa = make_float2(s0, s1);
                float2 rv = *(const float2*)(res_in + (size_t)grow * RCH + col);
                float r0 = rv.x + accr[mt][nq][rp * 2]     + sbias[384 + col];
                float r1 = rv.y + accr[mt][nq][rp * 2 + 1] + sbias[384 + col + 1];
                *(float2*)(res_out + (size_t)grow * RCH + col) = make_float2(r0, r1);
            }
}

// ---------------------------------------------------------------------------
// Tensor-core initial causal conv. 1024 CTAs x 64 rows, 256 thr, 2 CTAs/SM.
// K = 2048 = 32 taps x 64 ch; A-chunk for tap c = X panel rows [c, c+64).
__global__ void __launch_bounds__(256, 2) init_mma_kernel(
    const float* __restrict__ X, const __nv_bfloat16* __restrict__ wi,
    const float* __restrict__ B, float* __restrict__ res_out)
{
    extern __shared__ char smem[];
    float* sbias = (float*)smem;
    const uint32_t sbase = s2u(smem);
    const uint32_t sP = sbase + OFF_P;
    const uint32_t sW = sbase + OFF_IW;

    const int tid = threadIdx.x, wid = tid >> 5, lane = tid & 31;
    const int row0 = blockIdx.x * TM;
    const int batchStart = (row0 / T_LEN) * T_LEN;

    // prefetch tap 0 weights
    stage2(sW, wi, wi + (size_t)32 * 8192, tid);
    CP_COMMIT();

    for (int i = tid; i < 128; i += 256) sbias[i] = B[i];

    // ---- stage X panel rows [row0-31, row0+64) = 95 rows x 64 ch, bf16 hi/lo
    for (int idx = tid; idx < 95 * 8; idx += 256) {
        int row = idx >> 3, kg = (idx & 7) * 8;
        int srow = row0 - 31 + row;
        float v[8];
        if (srow >= batchStart) {
            const float4* sp = (const float4*)(X + (size_t)srow * 64 + kg);
            float4 a = sp[0], b2 = sp[1];
            v[0]=a.x; v[1]=a.y; v[2]=a.z; v[3]=a.w; v[4]=b2.x; v[5]=b2.y; v[6]=b2.z; v[7]=b2.w;
        } else {
            #pragma unroll
            for (int q = 0; q < 8; q++) v[q] = 0.f;
        }
        uint4 hp, lp;
        uint32_t* hw = (uint32_t*)&hp;
        uint32_t* lw = (uint32_t*)&lp;
        #pragma unroll
        for (int q = 0; q < 4; q++) {
            __nv_bfloat16 h0 = __float2bfloat16(v[2*q]),   h1 = __float2bfloat16(v[2*q+1]);
            __nv_bfloat16 l0 = __float2bfloat16(v[2*q]   - __bfloat162float(h0));
            __nv_bfloat16 l1 = __float2bfloat16(v[2*q+1] - __bfloat162float(h1));
            hw[q] = (uint32_t)__bfloat16_as_ushort(h0) | ((uint32_t)__bfloat16_as_ushort(h1) << 16);
            lw[q] = (uint32_t)__bfloat16_as_ushort(l0) | ((uint32_t)__bfloat16_as_ushort(l1) << 16);
        }
        uint32_t dst = sP + row * 144 + kg * 2;
        STS128(dst, hp);
        STS128(dst + PLO_OFF, lp);
    }
    CP_WAIT_ALL();
    __syncthreads();

    const int mbase = (wid & 1) * 32;
    const int nbase = (wid >> 1) * 32;
    const int aRow = lane & 15, aCol = (lane >> 4) * 8;
    const int bm = lane >> 3;
    const int bRow = (lane & 7) + ((bm >> 1) * 8), bCol = (bm & 1) * 8;
    // A base for tap c: rows (c + 31 - 31 ... panel row index = c + m). Panel row r = global row0-31+r,
    // A[m][tap c] needs global row row0+m-31+c -> panel row m + c.
    const uint32_t aPan = sP + (mbase + aRow) * 144 + aCol * 2;
    const uint32_t bB = sW + (nbase + bRow) * W_STRIDE + bCol * 2;

    const int qrow = lane >> 2, qcol = (lane & 3) * 2;

    float acc[2][4][4];
    #pragma unroll
    for (int mt = 0; mt < 2; mt++)
        #pragma unroll
        for (int nq = 0; nq < 4; nq++)
            #pragma unroll
            for (int q = 0; q < 4; q++) acc[mt][nq][q] = 0.f;

    for (int c = 0; c < 32; c++) {
        if (c < 31) {
            stage2(sW + ((c + 1) & 1) * IW_BUF,
                   wi + (size_t)(c + 1) * 8192,
                   wi + (size_t)(32 + c + 1) * 8192, tid);
            CP_COMMIT();
            CP_WAIT_1();
        } else {
            CP_WAIT_0();
        }
        __syncthreads();
        uint32_t aB = aPan + (uint32_t)c * 144;
        uint32_t wb = bB + (uint32_t)(c & 1) * IW_BUF;
        COMPUTE_INIT(acc, aB, wb);
        __syncthreads();
    }

    // epilogue: out = acc + bias
    #pragma unroll
    for (int mt = 0; mt < 2; mt++)
        #pragma unroll
        for (int nq = 0; nq < 4; nq++)
            #pragma unroll
            for (int rp = 0; rp < 2; rp++) {
                int row = mbase + mt * 16 + qrow + rp * 8;
                int col = nbase + nq * 8 + qcol;
                int grow = row0 + row;
                float o0 = acc[mt][nq][rp * 2]     + sbias[col];
                float o1 = acc[mt][nq][rp * 2 + 1] + sbias[col + 1];
                *(float2*)(res_out + (size_t)grow * RCH + col) = make_float2(o0, o1);
            }
}

// ---------------------------------------------------------------------------
// Post chain: 1024 threads/block (32 warps/SM) to hide the serial shfl chain.
__global__ void __launch_bounds__(1024) post_kernel(
    const float* __restrict__ out_acc,
    const float* __restrict__ s0w, const float* __restrict__ s0b,
    const float* __restrict__ srw, const float* __restrict__ srb,
    const float* __restrict__ fnw, const float* __restrict__ fnb,
    float* __restrict__ y)
{
    extern __shared__ float sm[];
    float* w0 = sm;
    float* wr = w0 + 4096;
    float* wf = wr + 31744;
    float* b0 = wf + 8192;
    float* br = b0 + 32;
    float* bf = br + 992;

    const int tid = threadIdx.x;
    for (int i = tid; i < 4096;  i += blockDim.x) w0[i] = s0w[i];
    for (int i = tid; i < 31744; i += blockDim.x) wr[i] = srw[i];
    for (int i = tid; i < 8192;  i += blockDim.x) wf[i] = fnw[i];
    for (int i = tid; i < 32;    i += blockDim.x) b0[i] = s0b[i];
    for (int i = tid; i < 992;   i += blockDim.x) br[i] = srb[i];
    for (int i = tid; i < 256;   i += blockDim.x) bf[i] = fnb[i];
    __syncthreads();

    const int warp = tid >> 5, lane = tid & 31;
    const int nwarp = blockDim.x >> 5;

    for (int pr = blockIdx.x * nwarp + warp; pr < BT / 2; pr += gridDim.x * nwarp) {
        const int rowA = pr * 2, rowB = pr * 2 + 1;
        float4 xa = ((const float4*)(out_acc + (size_t)rowA * RCH))[lane];
        float4 xb = ((const float4*)(out_acc + (size_t)rowB * RCH))[lane];
        xa.x = fmaxf(xa.x, 0.f); xa.y = fmaxf(xa.y, 0.f); xa.z = fmaxf(xa.z, 0.f); xa.w = fmaxf(xa.w, 0.f);
        xb.x = fmaxf(xb.x, 0.f); xb.y = fmaxf(xb.y, 0.f); xb.z = fmaxf(xb.z, 0.f); xb.w = fmaxf(xb.w, 0.f);
        ull xp0 = pk2(xa.x, xb.x), xp1 = pk2(xa.y, xb.y);
        ull xp2 = pk2(xa.z, xb.z), xp3 = pk2(xa.w, xb.w);

        float bb = b0[lane];
        ull h = pk2(bb, bb);
        #pragma unroll
        for (int s = 0; s < 32; s++) {
            ull v0 = __shfl_sync(0xffffffffu, xp0, s);
            ull v1 = __shfl_sync(0xffffffffu, xp1, s);
            ull v2 = __shfl_sync(0xffffffffu, xp2, s);
            ull v3 = __shfl_sync(0xffffffffu, xp3, s);
            float wv0 = w0[(s*4+0)*32 + lane];
            float wv1 = w0[(s*4+1)*32 + lane];
            float wv2 = w0[(s*4+2)*32 + lane];
            float wv3 = w0[(s*4+3)*32 + lane];
            fma2(h, v0, pk2(wv0, wv0));
            fma2(h, v1, pk2(wv1, wv1));
            fma2(h, v2, pk2(wv2, wv2));
            fma2(h, v3, pk2(wv3, wv3));
        }
        for (int li = 0; li < 31; li++) {
            float hl, hh; upk2(h, hl, hh);
            ull rv = pk2(fmaxf(hl, 0.f), fmaxf(hh, 0.f));
            const float* wp = wr + li * 1024;
            float bl = br[li*32 + lane];
            ull ha = pk2(bl, bl);
            ull hb = pk2(0.f, 0.f);
            #pragma unroll
            for (int s = 0; s < 32; s += 2) {
                ull ra  = __shfl_sync(0xffffffffu, rv, s);
                ull rb2 = __shfl_sync(0xffffffffu, rv, s + 1);
                float wA = wp[(s    )*32 + lane];
                float wB = wp[(s + 1)*32 + lane];
                fma2(ha, ra,  pk2(wA, wA));
                fma2(hb, rb2, pk2(wB, wB));
            }
            h = add2(ha, hb);
        }
        float hl, hh; upk2(h, hl, hh);
        ull rv = pk2(fmaxf(hl, 0.f), fmaxf(hh, 0.f));
        ull accP[8];
        #pragma unroll
        for (int u = 0; u < 8; u++) {
            float b = bf[lane*8 + u];
            accP[u] = pk2(b, b);
        }
        #pragma unroll
        for (int s = 0; s < 32; s++) {
            ull rs = __shfl_sync(0xffffffffu, rv, s);
            const float* wp = wf + s*256 + lane*8;
            float4 wq0 = *(const float4*)wp;
            float4 wq1 = *(const float4*)(wp + 4);
            fma2(accP[0], rs, pk2(wq0.x, wq0.x));
            fma2(accP[1], rs, pk2(wq0.y, wq0.y));
            fma2(accP[2], rs, pk2(wq0.z, wq0.z));
            fma2(accP[3], rs, pk2(wq0.w, wq0.w));
            fma2(accP[4], rs, pk2(wq1.x, wq1.x));
            fma2(accP[5], rs, pk2(wq1.y, wq1.y));
            fma2(accP[6], rs, pk2(wq1.z, wq1.z));
            fma2(accP[7], rs, pk2(wq1.w, wq1.w));
        }
        float oa[8], ob[8];
        #pragma unroll
        for (int u = 0; u < 8; u++) upk2(accP[u], oa[u], ob[u]);
        float4* ya = (float4*)(y + (size_t)rowA * 256 + lane * 8);
        ya[0] = make_float4(oa[0], oa[1], oa[2], oa[3]);
        ya[1] = make_float4(oa[4], oa[5], oa[6], oa[7]);
        float4* yb = (float4*)(y + (size_t)rowB * 256 + lane * 8);
        yb[0] = make_float4(ob[0], ob[1], ob[2], ob[3]);
        yb[1] = make_float4(ob[4], ob[5], ob[6], ob[7]);
    }
}

// ---------------------------------------------------------------------------
extern "C" void kernel_launch(void* const* d_in, const int* in_sizes, int n_in,
                              void* d_out, int out_size)
{
    const float* X       = (const float*)d_in[0];
    const float* init_w  = (const float*)d_in[1];
    const float* init_b  = (const float*)d_in[2];
    const float* f_w     = (const float*)d_in[3];
    const float* f_b     = (const float*)d_in[4];
    const float* g_w     = (const float*)d_in[5];
    const float* g_b     = (const float*)d_in[6];
    const float* skip_w  = (const float*)d_in[7];
    const float* skip_b  = (const float*)d_in[8];
    const float* res_w   = (const float*)d_in[9];
    const float* res_b   = (const float*)d_in[10];
    const float* skip0_w = (const float*)d_in[11];
    const float* skip0_b = (const float*)d_in[12];
    const float* skipr_w = (const float*)d_in[13];
    const float* skipr_b = (const float*)d_in[14];
    const float* final_w = (const float*)d_in[15];
    const float* final_b = (const float*)d_in[16];
    float* y = (float*)d_out;

    float *resA, *resB, *outacc;
    __nv_bfloat16 *wfg, *wsr, *wi;
    cudaGetSymbolAddress((void**)&resA,   g_resA);
    cudaGetSymbolAddress((void**)&resB,   g_resB);
    cudaGetSymbolAddress((void**)&outacc, g_outacc);
    cudaGetSymbolAddress((void**)&wfg,    g_wfg);
    cudaGetSymbolAddress((void**)&wsr,    g_wsr);
    cudaGetSymbolAddress((void**)&wi,     g_wi);

    const int POST_SMEM = (4096 + 31744 + 8192 + 32 + 992 + 256) * 4;
    cudaFuncSetAttribute(init_mma_kernel, cudaFuncAttributeMaxDynamicSharedMemorySize, ISMEM);
    cudaFuncSetAttribute(tlayer_kernel,   cudaFuncAttributeMaxDynamicSharedMemorySize, LSMEM);
    cudaFuncSetAttribute(post_kernel,     cudaFuncAttributeMaxDynamicSharedMemorySize, POST_SMEM);

    prep_kernel<<<544, 256>>>(f_w, g_w, skip_w, res_w, init_w);
    init_mma_kernel<<<BT / TM, 256, ISMEM>>>(X, wi, init_b, resA);

    static const int DIL[20] = {1,2,4,8,16,32,64,128,256,512,
                                1,2,4,8,16,32,64,128,256,512};
    for (int i = 0; i < 20; i++) {
        const float* rin  = (i & 1) ? resB : resA;
        float*       rout = (i & 1) ? resA : resB;
        tlayer_kernel<<<BT / TM, 256, LSMEM>>>(
            rin, rout, outacc,
            wfg + (size_t)i * 16 * 8192, wsr + (size_t)i * 8 * 8192,
            f_b + i * RCH, g_b + i * RCH, skip_b + i * RCH, res_b + i * RCH,
            DIL[i], (i == 0) ? 1 : 0);
    }

    post_kernel<<<296, 1024, POST_SMEM>>>(outacc, skip0_w, skip0_b,
                                          skipr_w, skipr_b, final_w, final_b, y);
}